// round 3
// baseline (speedup 1.0000x reference)
#include <cuda_runtime.h>
#include <cstddef>

// Problem dims (fixed by the reference)
#define BATCH 32
#define SEQ   1024
#define DIN   256
#define HID   512
#define MTOT  (BATCH * SEQ)   // 32768

// Scratch in __device__ globals (allocation-free rule)
__device__ float g_q[(size_t)BATCH * SEQ * HID];
__device__ float g_k[(size_t)BATCH * SEQ * HID];
__device__ float g_v[(size_t)BATCH * SEQ * HID];
__device__ float g_s[(size_t)BATCH * SEQ * SEQ];
__device__ float g_o[(size_t)BATCH * SEQ * HID];

// ---------------------------------------------------------------------------
// Tiled GEMM bodies: 64x64 tile, BK=16, 256 threads, 4x4 per-thread micro-tile
// ---------------------------------------------------------------------------

// C[m,n] = act( sum_k A[m,k] * B[n,k] + bias[n] )   (both K-major, "NT")
__device__ __forceinline__ void gemm_nt_body(
    const float* __restrict__ A, const float* __restrict__ Bm,
    const float* __restrict__ bias, float* __restrict__ C,
    int M, int Nn, int K, int m0, int n0, bool relu)
{
    __shared__ float As[16][64];
    __shared__ float Bs[16][64];

    const int t  = threadIdx.x;       // 0..255
    const int tr = t >> 4;            // 0..15 (row group)
    const int tc = t & 15;            // 0..15 (col group)
    const int lrow = t >> 2;          // 0..63 for loads
    const int lk   = (t & 3) << 2;    // 0,4,8,12

    float acc[4][4];
#pragma unroll
    for (int i = 0; i < 4; i++)
#pragma unroll
        for (int j = 0; j < 4; j++) acc[i][j] = 0.f;

    for (int kt = 0; kt < K; kt += 16) {
        float4 a4 = *(const float4*)(A + (size_t)(m0 + lrow) * K + kt + lk);
        As[lk + 0][lrow] = a4.x; As[lk + 1][lrow] = a4.y;
        As[lk + 2][lrow] = a4.z; As[lk + 3][lrow] = a4.w;
        float4 b4 = *(const float4*)(Bm + (size_t)(n0 + lrow) * K + kt + lk);
        Bs[lk + 0][lrow] = b4.x; Bs[lk + 1][lrow] = b4.y;
        Bs[lk + 2][lrow] = b4.z; Bs[lk + 3][lrow] = b4.w;
        __syncthreads();
#pragma unroll
        for (int k = 0; k < 16; k++) {
            float4 a = *(const float4*)&As[k][tr * 4];
            float4 b = *(const float4*)&Bs[k][tc * 4];
            acc[0][0] += a.x * b.x; acc[0][1] += a.x * b.y; acc[0][2] += a.x * b.z; acc[0][3] += a.x * b.w;
            acc[1][0] += a.y * b.x; acc[1][1] += a.y * b.y; acc[1][2] += a.y * b.z; acc[1][3] += a.y * b.w;
            acc[2][0] += a.z * b.x; acc[2][1] += a.z * b.y; acc[2][2] += a.z * b.z; acc[2][3] += a.z * b.w;
            acc[3][0] += a.w * b.x; acc[3][1] += a.w * b.y; acc[3][2] += a.w * b.z; acc[3][3] += a.w * b.w;
        }
        __syncthreads();
    }

    float4 bia = make_float4(0.f, 0.f, 0.f, 0.f);
    if (bias) bia = *(const float4*)(bias + n0 + tc * 4);
#pragma unroll
    for (int i = 0; i < 4; i++) {
        float4 r;
        r.x = acc[i][0] + bia.x; r.y = acc[i][1] + bia.y;
        r.z = acc[i][2] + bia.z; r.w = acc[i][3] + bia.w;
        if (relu) {
            r.x = fmaxf(r.x, 0.f); r.y = fmaxf(r.y, 0.f);
            r.z = fmaxf(r.z, 0.f); r.w = fmaxf(r.w, 0.f);
        }
        *(float4*)(C + (size_t)(m0 + tr * 4 + i) * Nn + n0 + tc * 4) = r;
    }
}

// C[m,n] = sum_k A[m,k] * B[k,n]   ("NN")
__device__ __forceinline__ void gemm_nn_body(
    const float* __restrict__ A, const float* __restrict__ Bm,
    float* __restrict__ C, int M, int Nn, int K, int m0, int n0)
{
    __shared__ float As[16][64];
    __shared__ float Bs[16][64];

    const int t  = threadIdx.x;
    const int tr = t >> 4;
    const int tc = t & 15;
    const int lrow = t >> 2;          // A-load row 0..63
    const int lk   = (t & 3) << 2;
    const int brow = t >> 4;          // B-load k-row 0..15
    const int bnc  = (t & 15) << 2;   // B-load col 0..60

    float acc[4][4];
#pragma unroll
    for (int i = 0; i < 4; i++)
#pragma unroll
        for (int j = 0; j < 4; j++) acc[i][j] = 0.f;

    for (int kt = 0; kt < K; kt += 16) {
        float4 a4 = *(const float4*)(A + (size_t)(m0 + lrow) * K + kt + lk);
        As[lk + 0][lrow] = a4.x; As[lk + 1][lrow] = a4.y;
        As[lk + 2][lrow] = a4.z; As[lk + 3][lrow] = a4.w;
        float4 b4 = *(const float4*)(Bm + (size_t)(kt + brow) * Nn + n0 + bnc);
        *(float4*)&Bs[brow][bnc] = b4;
        __syncthreads();
#pragma unroll
        for (int k = 0; k < 16; k++) {
            float4 a = *(const float4*)&As[k][tr * 4];
            float4 b = *(const float4*)&Bs[k][tc * 4];
            acc[0][0] += a.x * b.x; acc[0][1] += a.x * b.y; acc[0][2] += a.x * b.z; acc[0][3] += a.x * b.w;
            acc[1][0] += a.y * b.x; acc[1][1] += a.y * b.y; acc[1][2] += a.y * b.z; acc[1][3] += a.y * b.w;
            acc[2][0] += a.z * b.x; acc[2][1] += a.z * b.y; acc[2][2] += a.z * b.z; acc[2][3] += a.z * b.w;
            acc[3][0] += a.w * b.x; acc[3][1] += a.w * b.y; acc[3][2] += a.w * b.z; acc[3][3] += a.w * b.w;
        }
        __syncthreads();
    }

#pragma unroll
    for (int i = 0; i < 4; i++) {
        float4 r = make_float4(acc[i][0], acc[i][1], acc[i][2], acc[i][3]);
        *(float4*)(C + (size_t)(m0 + tr * 4 + i) * Nn + n0 + tc * 4) = r;
    }
}

// ---------------------------------------------------------------------------
// Kernels
// ---------------------------------------------------------------------------

// z=0 -> q, z=1 -> k, z=2 -> v. relu(h @ W^T + b), M=32768, N=512, K=256
__global__ void qkv_kernel(const float* __restrict__ h,
                           const float* __restrict__ Wq, const float* __restrict__ bq,
                           const float* __restrict__ Wk, const float* __restrict__ bk,
                           const float* __restrict__ Wv, const float* __restrict__ bv)
{
    const float* W; const float* bia; float* out;
    if (blockIdx.z == 0)      { W = Wq; bia = bq; out = g_q; }
    else if (blockIdx.z == 1) { W = Wk; bia = bk; out = g_k; }
    else                      { W = Wv; bia = bv; out = g_v; }
    gemm_nt_body(h, W, bia, out, MTOT, HID, DIN,
                 blockIdx.y * 64, blockIdx.x * 64, true);
}

// S[b] = Q[b] @ K[b]^T : M=N=1024, K=512 per batch
__global__ void scores_kernel()
{
    int b = blockIdx.z;
    const float* Q = g_q + (size_t)b * SEQ * HID;
    const float* K = g_k + (size_t)b * SEQ * HID;
    float* S = g_s + (size_t)b * SEQ * SEQ;
    gemm_nt_body(Q, K, nullptr, S, SEQ, SEQ, HID,
                 blockIdx.y * 64, blockIdx.x * 64, false);
}

// Row softmax over g_s, one block (256 threads) per row of 1024
__global__ void softmax_kernel()
{
    __shared__ float red[8];
    float* row = g_s + (size_t)blockIdx.x * SEQ;
    const int t = threadIdx.x;
    const int lane = t & 31, warp = t >> 5;

    float4 v = *(const float4*)(row + t * 4);
    float m = fmaxf(fmaxf(v.x, v.y), fmaxf(v.z, v.w));
#pragma unroll
    for (int o = 16; o > 0; o >>= 1) m = fmaxf(m, __shfl_xor_sync(0xffffffffu, m, o));
    if (lane == 0) red[warp] = m;
    __syncthreads();
    if (warp == 0) {
        float mm = red[lane & 7];
#pragma unroll
        for (int o = 4; o > 0; o >>= 1) mm = fmaxf(mm, __shfl_xor_sync(0xffffffffu, mm, o));
        if (lane == 0) red[0] = mm;
    }
    __syncthreads();
    m = red[0];
    __syncthreads();   // before reusing red[] for the sum

    v.x = expf(v.x - m); v.y = expf(v.y - m);
    v.z = expf(v.z - m); v.w = expf(v.w - m);
    float s = v.x + v.y + v.z + v.w;
#pragma unroll
    for (int o = 16; o > 0; o >>= 1) s += __shfl_xor_sync(0xffffffffu, s, o);
    if (lane == 0) red[warp] = s;
    __syncthreads();
    if (warp == 0) {
        float ss = red[lane & 7];
#pragma unroll
        for (int o = 4; o > 0; o >>= 1) ss += __shfl_xor_sync(0xffffffffu, ss, o);
        if (lane == 0) red[0] = ss;
    }
    __syncthreads();
    float inv = 1.0f / red[0];
    v.x *= inv; v.y *= inv; v.z *= inv; v.w *= inv;
    *(float4*)(row + t * 4) = v;
}

// O[b] = P[b] @ V[b] : M=1024, N=512, K=1024 per batch (NN)
__global__ void pv_kernel()
{
    int b = blockIdx.z;
    const float* P = g_s + (size_t)b * SEQ * SEQ;
    const float* V = g_v + (size_t)b * SEQ * HID;
    float* O = g_o + (size_t)b * SEQ * HID;
    gemm_nn_body(P, V, O, SEQ, HID, SEQ, blockIdx.y * 64, blockIdx.x * 64);
}

// out = relu(O @ Wo^T + bo) : M=32768, N=256, K=512
__global__ void outproj_kernel(const float* __restrict__ Wo,
                               const float* __restrict__ bo,
                               float* __restrict__ out)
{
    gemm_nt_body(g_o, Wo, bo, out, MTOT, DIN, HID,
                 blockIdx.y * 64, blockIdx.x * 64, true);
}

// ---------------------------------------------------------------------------
// Launch
// ---------------------------------------------------------------------------
extern "C" void kernel_launch(void* const* d_in, const int* in_sizes, int n_in,
                              void* d_out, int out_size)
{
    const float* h  = (const float*)d_in[0];
    const float* Wv = (const float*)d_in[1];
    const float* bv = (const float*)d_in[2];
    const float* Wk = (const float*)d_in[3];
    const float* bk = (const float*)d_in[4];
    const float* Wq = (const float*)d_in[5];
    const float* bq = (const float*)d_in[6];
    const float* Wo = (const float*)d_in[7];
    const float* bo = (const float*)d_in[8];
    float* out = (float*)d_out;

    dim3 gQKV(HID / 64, MTOT / 64, 3);
    qkv_kernel<<<gQKV, 256>>>(h, Wq, bq, Wk, bk, Wv, bv);

    dim3 gS(SEQ / 64, SEQ / 64, BATCH);
    scores_kernel<<<gS, 256>>>();

    softmax_kernel<<<BATCH * SEQ, 256>>>();

    dim3 gPV(HID / 64, SEQ / 64, BATCH);
    pv_kernel<<<gPV, 256>>>();

    dim3 gO(DIN / 64, MTOT / 64, 1);
    outproj_kernel<<<gO, 256>>>(Wo, bo, out);
}

// round 5
// speedup vs baseline: 5.3559x; 5.3559x over previous
#include <cuda_runtime.h>
#include <cstddef>
#include <cstdint>

// Problem dims (fixed by the reference)
#define BATCH 32
#define SEQ   1024
#define DIN   256
#define HID   512
#define MTOT  (BATCH * SEQ)   // 32768

// GEMM tiling
#define BM 128
#define BN 64
#define BK 16
#define AS_STRIDE 20   // 128 rows x 20 floats (pad for conflict-free frags)
#define BS_NT_STRIDE 20
#define BS_NN_STRIDE 72
#define AS_ELEMS (BM * AS_STRIDE)          // 2560
#define BS_ELEMS 1280                       // max(64*20, 16*72)

// Scratch in __device__ globals (allocation-free rule)
__device__ float g_q[(size_t)BATCH * SEQ * HID];
__device__ float g_k[(size_t)BATCH * SEQ * HID];
__device__ float g_v[(size_t)BATCH * SEQ * HID];
__device__ float g_s[(size_t)BATCH * SEQ * SEQ];
__device__ float g_o[(size_t)BATCH * SEQ * HID];

// ---------------------------------------------------------------------------
// PTX helpers
// ---------------------------------------------------------------------------
__device__ __forceinline__ void cp16(float* s, const float* g) {
    uint32_t sa = (uint32_t)__cvta_generic_to_shared(s);
    asm volatile("cp.async.cg.shared.global [%0], [%1], 16;\n" :: "r"(sa), "l"(g));
}
__device__ __forceinline__ void cp_commit() {
    asm volatile("cp.async.commit_group;\n");
}
__device__ __forceinline__ void cp_wait1() {
    asm volatile("cp.async.wait_group 1;\n");
}
__device__ __forceinline__ void cp_wait0() {
    asm volatile("cp.async.wait_group 0;\n");
}
__device__ __forceinline__ uint32_t tf32r(float x) {
    uint32_t u;
    asm("cvt.rna.tf32.f32 %0, %1;\n" : "=r"(u) : "f"(x));
    return u;
}
__device__ __forceinline__ void mma_tf32(float& c0, float& c1, float& c2, float& c3,
                                         uint32_t a0, uint32_t a1, uint32_t a2, uint32_t a3,
                                         uint32_t b0, uint32_t b1) {
    asm volatile(
        "mma.sync.aligned.m16n8k8.row.col.f32.tf32.tf32.f32 "
        "{%0,%1,%2,%3}, {%4,%5,%6,%7}, {%8,%9}, {%0,%1,%2,%3};\n"
        : "+f"(c0), "+f"(c1), "+f"(c2), "+f"(c3)
        : "r"(a0), "r"(a1), "r"(a2), "r"(a3), "r"(b0), "r"(b1));
}

// ---------------------------------------------------------------------------
// Tensor-core GEMM body.
//   NT=true : C[M,N] = act(A[M,K] * B[N,K]^T + bias)
//   NT=false: C[M,N] = A[M,K] * B[K,N]          (bias must be nullptr)
// Block tile 128x64, BK=16, 256 threads, warp tile 32x32 (m16n8k8 tf32 mma),
// 2-stage cp.async pipeline.
// ---------------------------------------------------------------------------
template<bool NT>
__device__ __forceinline__ void mma_gemm_body(
    const float* __restrict__ A, const float* __restrict__ B,
    const float* __restrict__ bias, float* __restrict__ Cout,
    int N, int K, int m0, int n0, bool relu)
{
    __shared__ float As[2 * AS_ELEMS];
    __shared__ float Bs[2 * BS_ELEMS];

    const int t    = threadIdx.x;
    const int lane = t & 31;
    const int warp = t >> 5;
    const int wm   = (warp >> 1) * 32;   // 0,32,64,96
    const int wn   = (warp & 1) * 32;    // 0,32
    const int g4   = lane >> 2;          // 0..7
    const int l4   = lane & 3;           // 0..3

    // staging indices
    const int ar = t >> 2;               // 0..63
    const int ak = (t & 3) << 2;         // 0,4,8,12
    const int bk2 = t >> 4;              // 0..15  (NN)
    const int bn2 = (t & 15) << 2;       // 0..60  (NN)

    float acc[2][4][4];
#pragma unroll
    for (int mt = 0; mt < 2; mt++)
#pragma unroll
        for (int nt = 0; nt < 4; nt++)
#pragma unroll
            for (int i = 0; i < 4; i++) acc[mt][nt][i] = 0.f;

    const int nchunks = K >> 4;

    // --- stage helper ---
    auto stage = [&](int s, int kt) {
        float* Ad = As + s * AS_ELEMS;
        float* Bd = Bs + s * BS_ELEMS;
        cp16(Ad + ar * AS_STRIDE + ak,          A + (size_t)(m0 + ar) * K + kt + ak);
        cp16(Ad + (ar + 64) * AS_STRIDE + ak,   A + (size_t)(m0 + ar + 64) * K + kt + ak);
        if (NT) {
            cp16(Bd + ar * BS_NT_STRIDE + ak,   B + (size_t)(n0 + ar) * K + kt + ak);
        } else {
            cp16(Bd + bk2 * BS_NN_STRIDE + bn2, B + (size_t)(kt + bk2) * N + n0 + bn2);
        }
    };

    stage(0, 0);
    cp_commit();

    for (int c = 0; c < nchunks; ++c) {
        const int s = c & 1;
        if (c + 1 < nchunks) {
            stage(s ^ 1, (c + 1) << 4);
            cp_commit();
            cp_wait1();
        } else {
            cp_wait0();
        }
        __syncthreads();

        const float* Asb = As + s * AS_ELEMS;
        const float* Bsb = Bs + s * BS_ELEMS;

#pragma unroll
        for (int ks = 0; ks < 2; ++ks) {
            const int k8 = ks * 8;
            uint32_t af[2][4];
#pragma unroll
            for (int mt = 0; mt < 2; mt++) {
                const int r  = wm + mt * 16 + g4;
                const int cc = k8 + l4;
                af[mt][0] = tf32r(Asb[r * AS_STRIDE + cc]);
                af[mt][1] = tf32r(Asb[(r + 8) * AS_STRIDE + cc]);
                af[mt][2] = tf32r(Asb[r * AS_STRIDE + cc + 4]);
                af[mt][3] = tf32r(Asb[(r + 8) * AS_STRIDE + cc + 4]);
            }
            uint32_t bf[4][2];
#pragma unroll
            for (int nt = 0; nt < 4; nt++) {
                const int col = wn + nt * 8 + g4;
                const int kk  = k8 + l4;
                if (NT) {
                    bf[nt][0] = tf32r(Bsb[col * BS_NT_STRIDE + kk]);
                    bf[nt][1] = tf32r(Bsb[col * BS_NT_STRIDE + kk + 4]);
                } else {
                    bf[nt][0] = tf32r(Bsb[kk * BS_NN_STRIDE + col]);
                    bf[nt][1] = tf32r(Bsb[(kk + 4) * BS_NN_STRIDE + col]);
                }
            }
#pragma unroll
            for (int mt = 0; mt < 2; mt++)
#pragma unroll
                for (int nt = 0; nt < 4; nt++)
                    mma_tf32(acc[mt][nt][0], acc[mt][nt][1], acc[mt][nt][2], acc[mt][nt][3],
                             af[mt][0], af[mt][1], af[mt][2], af[mt][3],
                             bf[nt][0], bf[nt][1]);
        }
        __syncthreads();
    }

    // --- epilogue ---
#pragma unroll
    for (int mt = 0; mt < 2; mt++) {
        const int r = m0 + wm + mt * 16 + g4;
#pragma unroll
        for (int nt = 0; nt < 4; nt++) {
            const int col = n0 + wn + nt * 8 + 2 * l4;
            float bx = 0.f, by = 0.f;
            if (bias) { bx = bias[col]; by = bias[col + 1]; }
            float v0 = acc[mt][nt][0] + bx;
            float v1 = acc[mt][nt][1] + by;
            float v2 = acc[mt][nt][2] + bx;
            float v3 = acc[mt][nt][3] + by;
            if (relu) {
                v0 = fmaxf(v0, 0.f); v1 = fmaxf(v1, 0.f);
                v2 = fmaxf(v2, 0.f); v3 = fmaxf(v3, 0.f);
            }
            *(float2*)(Cout + (size_t)r * N + col)       = make_float2(v0, v1);
            *(float2*)(Cout + (size_t)(r + 8) * N + col) = make_float2(v2, v3);
        }
    }
}

// ---------------------------------------------------------------------------
// Kernels
// ---------------------------------------------------------------------------

// z=0 -> q, z=1 -> k, z=2 -> v : relu(h @ W^T + b)  M=32768, N=512, K=256
__global__ void qkv_kernel(const float* __restrict__ h,
                           const float* __restrict__ Wq, const float* __restrict__ bq,
                           const float* __restrict__ Wk, const float* __restrict__ bk,
                           const float* __restrict__ Wv, const float* __restrict__ bv)
{
    const float* W; const float* bia; float* out;
    if (blockIdx.z == 0)      { W = Wq; bia = bq; out = g_q; }
    else if (blockIdx.z == 1) { W = Wk; bia = bk; out = g_k; }
    else                      { W = Wv; bia = bv; out = g_v; }
    mma_gemm_body<true>(h, W, bia, out, HID, DIN,
                        blockIdx.y * BM, blockIdx.x * BN, true);
}

// S[b] = Q[b] @ K[b]^T : M=N=1024, K=512 per batch
__global__ void scores_kernel()
{
    const int b = blockIdx.z;
    const float* Q = g_q + (size_t)b * SEQ * HID;
    const float* K = g_k + (size_t)b * SEQ * HID;
    float* S = g_s + (size_t)b * SEQ * SEQ;
    mma_gemm_body<true>(Q, K, nullptr, S, SEQ, HID,
                        blockIdx.y * BM, blockIdx.x * BN, false);
}

// Row softmax over g_s, one block (256 threads) per row of 1024
__global__ void softmax_kernel()
{
    __shared__ float red[8];
    float* row = g_s + (size_t)blockIdx.x * SEQ;
    const int t = threadIdx.x;
    const int lane = t & 31, warp = t >> 5;

    float4 v = *(const float4*)(row + t * 4);
    float m = fmaxf(fmaxf(v.x, v.y), fmaxf(v.z, v.w));
#pragma unroll
    for (int o = 16; o > 0; o >>= 1) m = fmaxf(m, __shfl_xor_sync(0xffffffffu, m, o));
    if (lane == 0) red[warp] = m;
    __syncthreads();
    if (warp == 0) {
        float mm = red[lane & 7];
#pragma unroll
        for (int o = 4; o > 0; o >>= 1) mm = fmaxf(mm, __shfl_xor_sync(0xffffffffu, mm, o));
        if (lane == 0) red[0] = mm;
    }
    __syncthreads();
    m = red[0];
    __syncthreads();

    v.x = expf(v.x - m); v.y = expf(v.y - m);
    v.z = expf(v.z - m); v.w = expf(v.w - m);
    float s = v.x + v.y + v.z + v.w;
#pragma unroll
    for (int o = 16; o > 0; o >>= 1) s += __shfl_xor_sync(0xffffffffu, s, o);
    if (lane == 0) red[warp] = s;
    __syncthreads();
    if (warp == 0) {
        float ss = red[lane & 7];
#pragma unroll
        for (int o = 4; o > 0; o >>= 1) ss += __shfl_xor_sync(0xffffffffu, ss, o);
        if (lane == 0) red[0] = ss;
    }
    __syncthreads();
    float inv = 1.0f / red[0];
    v.x *= inv; v.y *= inv; v.z *= inv; v.w *= inv;
    *(float4*)(row + t * 4) = v;
}

// O[b] = P[b] @ V[b] : M=1024, N=512, K=1024 per batch (NN)
__global__ void pv_kernel()
{
    const int b = blockIdx.z;
    const float* P = g_s + (size_t)b * SEQ * SEQ;
    const float* V = g_v + (size_t)b * SEQ * HID;
    float* O = g_o + (size_t)b * SEQ * HID;
    mma_gemm_body<false>(P, V, nullptr, O, HID, SEQ,
                         blockIdx.y * BM, blockIdx.x * BN, false);
}

// out = relu(O @ Wo^T + bo) : M=32768, N=256, K=512
__global__ void outproj_kernel(const float* __restrict__ Wo,
                               const float* __restrict__ bo,
                               float* __restrict__ out)
{
    mma_gemm_body<true>(g_o, Wo, bo, out, DIN, HID,
                        blockIdx.y * BM, blockIdx.x * BN, true);
}

// ---------------------------------------------------------------------------
// Launch
// ---------------------------------------------------------------------------
extern "C" void kernel_launch(void* const* d_in, const int* in_sizes, int n_in,
                              void* d_out, int out_size)
{
    const float* h  = (const float*)d_in[0];
    const float* Wv = (const float*)d_in[1];
    const float* bv = (const float*)d_in[2];
    const float* Wk = (const float*)d_in[3];
    const float* bk = (const float*)d_in[4];
    const float* Wq = (const float*)d_in[5];
    const float* bq = (const float*)d_in[6];
    const float* Wo = (const float*)d_in[7];
    const float* bo = (const float*)d_in[8];
    float* out = (float*)d_out;

    dim3 gQKV(HID / BN, MTOT / BM, 3);
    qkv_kernel<<<gQKV, 256>>>(h, Wq, bq, Wk, bk, Wv, bv);

    dim3 gS(SEQ / BN, SEQ / BM, BATCH);
    scores_kernel<<<gS, 256>>>();

    softmax_kernel<<<BATCH * SEQ, 256>>>();

    dim3 gPV(HID / BN, SEQ / BM, BATCH);
    pv_kernel<<<gPV, 256>>>();

    dim3 gO(DIN / BN, MTOT / BM, 1);
    outproj_kernel<<<gO, 256>>>(Wo, bo, out);
}

// round 6
// speedup vs baseline: 5.4317x; 1.0142x over previous
#include <cuda_runtime.h>
#include <cstddef>
#include <cstdint>

// Problem dims (fixed by the reference)
#define BATCH 32
#define SEQ   1024
#define DIN   256
#define HID   512
#define MTOT  (BATCH * SEQ)   // 32768

// GEMM tiling: block 128x128, BK=16, 8 warps (2x4), warp tile 64x32
#define BM 128
#define BN 128
#define BK 16
#define AS_STRIDE 20      // (20*r + c) % 32 distinct across a fragment warp
#define BS_NT_STRIDE 20
#define BS_NN_STRIDE 136  // (8*k + n) % 32 distinct across all 32 lanes
#define AS_ELEMS (BM * AS_STRIDE)   // 2560
#define BS_ELEMS 2560               // max(128*20, 16*136=2176)

// Scratch in __device__ globals (allocation-free rule)
__device__ float g_q[(size_t)BATCH * SEQ * HID];
__device__ float g_k[(size_t)BATCH * SEQ * HID];
__device__ float g_v[(size_t)BATCH * SEQ * HID];
__device__ float g_s[(size_t)BATCH * SEQ * SEQ];
__device__ float g_o[(size_t)BATCH * SEQ * HID];

// ---------------------------------------------------------------------------
// PTX helpers
// ---------------------------------------------------------------------------
__device__ __forceinline__ uint32_t tf32r(float x) {
    uint32_t u;
    asm("cvt.rna.tf32.f32 %0, %1;\n" : "=r"(u) : "f"(x));
    return u;
}
__device__ __forceinline__ uint4 tf32r4(float4 v) {
    uint4 r;
    r.x = tf32r(v.x); r.y = tf32r(v.y); r.z = tf32r(v.z); r.w = tf32r(v.w);
    return r;
}
__device__ __forceinline__ void mma_tf32(float& c0, float& c1, float& c2, float& c3,
                                         uint32_t a0, uint32_t a1, uint32_t a2, uint32_t a3,
                                         uint32_t b0, uint32_t b1) {
    asm volatile(
        "mma.sync.aligned.m16n8k8.row.col.f32.tf32.tf32.f32 "
        "{%0,%1,%2,%3}, {%4,%5,%6,%7}, {%8,%9}, {%0,%1,%2,%3};\n"
        : "+f"(c0), "+f"(c1), "+f"(c2), "+f"(c3)
        : "r"(a0), "r"(a1), "r"(a2), "r"(a3), "r"(b0), "r"(b1));
}

// ---------------------------------------------------------------------------
// Tensor-core GEMM body.
//   NT=true : C[M,N] = act(A[M,K] * B[N,K]^T + bias)
//   NT=false: C[M,N] = A[M,K] * B[K,N]          (bias must be nullptr)
// Pre-converted tf32 in smem; inner loop is pure LDS + MMA.
// Double-buffered smem, register prefetch of next chunk, one barrier/chunk.
// ---------------------------------------------------------------------------
template<bool NT>
__device__ __forceinline__ void mma_gemm_body(
    const float* __restrict__ A, const float* __restrict__ B,
    const float* __restrict__ bias, float* __restrict__ Cout,
    int N, int K, int m0, int n0, bool relu)
{
    __shared__ uint32_t As[2 * AS_ELEMS];
    __shared__ uint32_t Bs[2 * BS_ELEMS];

    const int t    = threadIdx.x;
    const int lane = t & 31;
    const int warp = t >> 5;
    const int wm   = (warp >> 2) * 64;   // 0,64
    const int wn   = (warp & 3) * 32;    // 0,32,64,96
    const int g4   = lane >> 2;          // 0..7
    const int l4   = lane & 3;           // 0..3

    // staging indices
    const int ar = t >> 2;               // 0..63 (A rows; also NT-B rows)
    const int ak = (t & 3) << 2;         // 0,4,8,12
    const int bkr = t >> 4;              // 0..15  (NN B k-row)
    const int bnc = (t & 15) << 2;       // 0..60  (NN B col group)

    float acc[4][4][4];
#pragma unroll
    for (int mt = 0; mt < 4; mt++)
#pragma unroll
        for (int nt = 0; nt < 4; nt++)
#pragma unroll
            for (int i = 0; i < 4; i++) acc[mt][nt][i] = 0.f;

    const int nchunks = K >> 4;

    // prefetch registers
    float4 ra0, ra1, rb0, rb1;

    auto ldg = [&](int kt) {
        ra0 = *(const float4*)(A + (size_t)(m0 + ar) * K + kt + ak);
        ra1 = *(const float4*)(A + (size_t)(m0 + ar + 64) * K + kt + ak);
        if (NT) {
            rb0 = *(const float4*)(B + (size_t)(n0 + ar) * K + kt + ak);
            rb1 = *(const float4*)(B + (size_t)(n0 + ar + 64) * K + kt + ak);
        } else {
            rb0 = *(const float4*)(B + (size_t)(kt + bkr) * N + n0 + bnc);
            rb1 = *(const float4*)(B + (size_t)(kt + bkr) * N + n0 + bnc + 64);
        }
    };
    auto sts = [&](int s) {
        uint32_t* Ad = As + s * AS_ELEMS;
        uint32_t* Bd = Bs + s * BS_ELEMS;
        *(uint4*)(Ad + ar * AS_STRIDE + ak)        = tf32r4(ra0);
        *(uint4*)(Ad + (ar + 64) * AS_STRIDE + ak) = tf32r4(ra1);
        if (NT) {
            *(uint4*)(Bd + ar * BS_NT_STRIDE + ak)        = tf32r4(rb0);
            *(uint4*)(Bd + (ar + 64) * BS_NT_STRIDE + ak) = tf32r4(rb1);
        } else {
            *(uint4*)(Bd + bkr * BS_NN_STRIDE + bnc)      = tf32r4(rb0);
            *(uint4*)(Bd + bkr * BS_NN_STRIDE + bnc + 64) = tf32r4(rb1);
        }
    };

    ldg(0);

    for (int c = 0; c < nchunks; ++c) {
        const int s = c & 1;
        sts(s);
        __syncthreads();
        if (c + 1 < nchunks) ldg((c + 1) << 4);

        const uint32_t* Asb = As + s * AS_ELEMS;
        const uint32_t* Bsb = Bs + s * BS_ELEMS;

#pragma unroll
        for (int ks = 0; ks < 2; ++ks) {
            const int k8 = ks * 8;
            uint32_t af[4][4];
#pragma unroll
            for (int mt = 0; mt < 4; mt++) {
                const int r  = wm + mt * 16 + g4;
                const int cc = k8 + l4;
                af[mt][0] = Asb[r * AS_STRIDE + cc];
                af[mt][1] = Asb[(r + 8) * AS_STRIDE + cc];
                af[mt][2] = Asb[r * AS_STRIDE + cc + 4];
                af[mt][3] = Asb[(r + 8) * AS_STRIDE + cc + 4];
            }
            uint32_t bf[4][2];
#pragma unroll
            for (int nt = 0; nt < 4; nt++) {
                const int col = wn + nt * 8 + g4;
                const int kk  = k8 + l4;
                if (NT) {
                    bf[nt][0] = Bsb[col * BS_NT_STRIDE + kk];
                    bf[nt][1] = Bsb[col * BS_NT_STRIDE + kk + 4];
                } else {
                    bf[nt][0] = Bsb[kk * BS_NN_STRIDE + col];
                    bf[nt][1] = Bsb[(kk + 4) * BS_NN_STRIDE + col];
                }
            }
#pragma unroll
            for (int mt = 0; mt < 4; mt++)
#pragma unroll
                for (int nt = 0; nt < 4; nt++)
                    mma_tf32(acc[mt][nt][0], acc[mt][nt][1], acc[mt][nt][2], acc[mt][nt][3],
                             af[mt][0], af[mt][1], af[mt][2], af[mt][3],
                             bf[nt][0], bf[nt][1]);
        }
        __syncthreads();
    }

    // --- epilogue ---
#pragma unroll
    for (int mt = 0; mt < 4; mt++) {
        const int r = m0 + wm + mt * 16 + g4;
#pragma unroll
        for (int nt = 0; nt < 4; nt++) {
            const int col = n0 + wn + nt * 8 + 2 * l4;
            float bx = 0.f, by = 0.f;
            if (bias) { bx = bias[col]; by = bias[col + 1]; }
            float v0 = acc[mt][nt][0] + bx;
            float v1 = acc[mt][nt][1] + by;
            float v2 = acc[mt][nt][2] + bx;
            float v3 = acc[mt][nt][3] + by;
            if (relu) {
                v0 = fmaxf(v0, 0.f); v1 = fmaxf(v1, 0.f);
                v2 = fmaxf(v2, 0.f); v3 = fmaxf(v3, 0.f);
            }
            *(float2*)(Cout + (size_t)r * N + col)       = make_float2(v0, v1);
            *(float2*)(Cout + (size_t)(r + 8) * N + col) = make_float2(v2, v3);
        }
    }
}

// ---------------------------------------------------------------------------
// Kernels
// ---------------------------------------------------------------------------

// z=0 -> q, z=1 -> k, z=2 -> v : relu(h @ W^T + b)  M=32768, N=512, K=256
__global__ void __launch_bounds__(256, 2)
qkv_kernel(const float* __restrict__ h,
           const float* __restrict__ Wq, const float* __restrict__ bq,
           const float* __restrict__ Wk, const float* __restrict__ bk,
           const float* __restrict__ Wv, const float* __restrict__ bv)
{
    const float* W; const float* bia; float* out;
    if (blockIdx.z == 0)      { W = Wq; bia = bq; out = g_q; }
    else if (blockIdx.z == 1) { W = Wk; bia = bk; out = g_k; }
    else                      { W = Wv; bia = bv; out = g_v; }
    mma_gemm_body<true>(h, W, bia, out, HID, DIN,
                        blockIdx.y * BM, blockIdx.x * BN, true);
}

// S[b] = Q[b] @ K[b]^T : M=N=1024, K=512 per batch
__global__ void __launch_bounds__(256, 2)
scores_kernel()
{
    const int b = blockIdx.z;
    const float* Q = g_q + (size_t)b * SEQ * HID;
    const float* K = g_k + (size_t)b * SEQ * HID;
    float* S = g_s + (size_t)b * SEQ * SEQ;
    mma_gemm_body<true>(Q, K, nullptr, S, SEQ, HID,
                        blockIdx.y * BM, blockIdx.x * BN, false);
}

// Row softmax over g_s, one block (256 threads) per row of 1024
__global__ void softmax_kernel()
{
    __shared__ float red[8];
    float* row = g_s + (size_t)blockIdx.x * SEQ;
    const int t = threadIdx.x;
    const int lane = t & 31, warp = t >> 5;

    float4 v = *(const float4*)(row + t * 4);
    float m = fmaxf(fmaxf(v.x, v.y), fmaxf(v.z, v.w));
#pragma unroll
    for (int o = 16; o > 0; o >>= 1) m = fmaxf(m, __shfl_xor_sync(0xffffffffu, m, o));
    if (lane == 0) red[warp] = m;
    __syncthreads();
    if (warp == 0) {
        float mm = red[lane & 7];
#pragma unroll
        for (int o = 4; o > 0; o >>= 1) mm = fmaxf(mm, __shfl_xor_sync(0xffffffffu, mm, o));
        if (lane == 0) red[0] = mm;
    }
    __syncthreads();
    m = red[0];
    __syncthreads();

    v.x = expf(v.x - m); v.y = expf(v.y - m);
    v.z = expf(v.z - m); v.w = expf(v.w - m);
    float s = v.x + v.y + v.z + v.w;
#pragma unroll
    for (int o = 16; o > 0; o >>= 1) s += __shfl_xor_sync(0xffffffffu, s, o);
    if (lane == 0) red[warp] = s;
    __syncthreads();
    if (warp == 0) {
        float ss = red[lane & 7];
#pragma unroll
        for (int o = 4; o > 0; o >>= 1) ss += __shfl_xor_sync(0xffffffffu, ss, o);
        if (lane == 0) red[0] = ss;
    }
    __syncthreads();
    float inv = 1.0f / red[0];
    v.x *= inv; v.y *= inv; v.z *= inv; v.w *= inv;
    *(float4*)(row + t * 4) = v;
}

// O[b] = P[b] @ V[b] : M=1024, N=512, K=1024 per batch (NN)
__global__ void __launch_bounds__(256, 2)
pv_kernel()
{
    const int b = blockIdx.z;
    const float* P = g_s + (size_t)b * SEQ * SEQ;
    const float* V = g_v + (size_t)b * SEQ * HID;
    float* O = g_o + (size_t)b * SEQ * HID;
    mma_gemm_body<false>(P, V, nullptr, O, HID, SEQ,
                         blockIdx.y * BM, blockIdx.x * BN, false);
}

// out = relu(O @ Wo^T + bo) : M=32768, N=256, K=512
__global__ void __launch_bounds__(256, 2)
outproj_kernel(const float* __restrict__ Wo,
               const float* __restrict__ bo,
               float* __restrict__ out)
{
    mma_gemm_body<true>(g_o, Wo, bo, out, DIN, HID,
                        blockIdx.y * BM, blockIdx.x * BN, true);
}

// ---------------------------------------------------------------------------
// Launch
// ---------------------------------------------------------------------------
extern "C" void kernel_launch(void* const* d_in, const int* in_sizes, int n_in,
                              void* d_out, int out_size)
{
    const float* h  = (const float*)d_in[0];
    const float* Wv = (const float*)d_in[1];
    const float* bv = (const float*)d_in[2];
    const float* Wk = (const float*)d_in[3];
    const float* bk = (const float*)d_in[4];
    const float* Wq = (const float*)d_in[5];
    const float* bq = (const float*)d_in[6];
    const float* Wo = (const float*)d_in[7];
    const float* bo = (const float*)d_in[8];
    float* out = (float*)d_out;

    dim3 gQKV(HID / BN, MTOT / BM, 3);
    qkv_kernel<<<gQKV, 256>>>(h, Wq, bq, Wk, bk, Wv, bv);

    dim3 gS(SEQ / BN, SEQ / BM, BATCH);
    scores_kernel<<<gS, 256>>>();

    softmax_kernel<<<BATCH * SEQ, 256>>>();

    dim3 gPV(HID / BN, SEQ / BM, BATCH);
    pv_kernel<<<gPV, 256>>>();

    dim3 gO(DIN / BN, MTOT / BM, 1);
    outproj_kernel<<<gO, 256>>>(Wo, bo, out);
}

// round 10
// speedup vs baseline: 6.0409x; 1.1122x over previous
#include <cuda_runtime.h>
#include <cstddef>
#include <cstdint>

// Problem dims (fixed by the reference)
#define BATCH 32
#define SEQ   1024
#define DIN   256
#define HID   512
#define MTOT  (BATCH * SEQ)   // 32768

// GEMM tiling: block 128x128, BK=16, 4 warps (2x2), warp tile 64x64
#define BM 128
#define BN 128
#define BK 16
#define AS_STRIDE 20      // (20*r + c) % 32 distinct across a fragment warp
#define BS_NT_STRIDE 20
#define BS_NN_STRIDE 136  // (136*k + n) % 32 = 8*l4+g4+c distinct across lanes
#define AS_ELEMS (BM * AS_STRIDE)   // 2560
#define BS_ELEMS 2560               // max(128*20, 16*136=2176)

// Scratch in __device__ globals (allocation-free rule)
__device__ float g_q[(size_t)BATCH * SEQ * HID];
__device__ float g_k[(size_t)BATCH * SEQ * HID];
__device__ float g_v[(size_t)BATCH * SEQ * HID];
__device__ float g_s[(size_t)BATCH * SEQ * SEQ];
__device__ float g_o[(size_t)BATCH * SEQ * HID];

// ---------------------------------------------------------------------------
// PTX helpers
// ---------------------------------------------------------------------------
__device__ __forceinline__ uint32_t tf32r(float x) {
    uint32_t u;
    asm("cvt.rna.tf32.f32 %0, %1;\n" : "=r"(u) : "f"(x));
    return u;
}
__device__ __forceinline__ uint4 tf32r4(float4 v) {
    uint4 r;
    r.x = tf32r(v.x); r.y = tf32r(v.y); r.z = tf32r(v.z); r.w = tf32r(v.w);
    return r;
}
__device__ __forceinline__ void mma_tf32(float& c0, float& c1, float& c2, float& c3,
                                         uint32_t a0, uint32_t a1, uint32_t a2, uint32_t a3,
                                         uint32_t b0, uint32_t b1) {
    asm volatile(
        "mma.sync.aligned.m16n8k8.row.col.f32.tf32.tf32.f32 "
        "{%0,%1,%2,%3}, {%4,%5,%6,%7}, {%8,%9}, {%0,%1,%2,%3};\n"
        : "+f"(c0), "+f"(c1), "+f"(c2), "+f"(c3)
        : "r"(a0), "r"(a1), "r"(a2), "r"(a3), "r"(b0), "r"(b1));
}

// ---------------------------------------------------------------------------
// Tensor-core GEMM body (register MMA, tf32).
//   NT=true : C[M,N] = act(A[M,K] * B[N,K]^T + bias)
//   NT=false: C[M,N] = A[M,K] * B[K,N]          (bias must be nullptr)
// Pre-converted tf32 in smem; inner loop is pure LDS + MMA.
// Double-buffered smem, register prefetch of next chunk, warp tile 64x64.
// ---------------------------------------------------------------------------
template<bool NT>
__device__ __forceinline__ void mma_gemm_body(
    const float* __restrict__ A, const float* __restrict__ B,
    const float* __restrict__ bias, float* __restrict__ Cout,
    int N, int K, int m0, int n0, bool relu)
{
    __shared__ uint32_t As[2 * AS_ELEMS];
    __shared__ uint32_t Bs[2 * BS_ELEMS];

    const int t    = threadIdx.x;       // 0..127
    const int lane = t & 31;
    const int warp = t >> 5;            // 0..3
    const int wm   = (warp >> 1) * 64;  // 0,64
    const int wn   = (warp & 1) * 64;   // 0,64
    const int g4   = lane >> 2;         // 0..7
    const int l4   = lane & 3;          // 0..3

    // staging indices
    const int ar = t >> 2;              // 0..31 (+32*i) A/NT-B rows
    const int ak = (t & 3) << 2;        // 0,4,8,12
    const int bkr = t >> 3;             // 0..15  (NN B k-row)
    const int bnc = (t & 7) << 2;       // 0..28  (NN B col base, +32*i)

    float acc[4][8][4];
#pragma unroll
    for (int mt = 0; mt < 4; mt++)
#pragma unroll
        for (int nt = 0; nt < 8; nt++)
#pragma unroll
            for (int i = 0; i < 4; i++) acc[mt][nt][i] = 0.f;

    const int nchunks = K >> 4;

    // prefetch registers (4 x float4 each operand)
    float4 ra[4], rb[4];

    auto ldg = [&](int kt) {
#pragma unroll
        for (int i = 0; i < 4; i++)
            ra[i] = *(const float4*)(A + (size_t)(m0 + ar + 32 * i) * K + kt + ak);
        if (NT) {
#pragma unroll
            for (int i = 0; i < 4; i++)
                rb[i] = *(const float4*)(B + (size_t)(n0 + ar + 32 * i) * K + kt + ak);
        } else {
#pragma unroll
            for (int i = 0; i < 4; i++)
                rb[i] = *(const float4*)(B + (size_t)(kt + bkr) * N + n0 + bnc + 32 * i);
        }
    };
    auto sts = [&](int s) {
        uint32_t* Ad = As + s * AS_ELEMS;
        uint32_t* Bd = Bs + s * BS_ELEMS;
#pragma unroll
        for (int i = 0; i < 4; i++)
            *(uint4*)(Ad + (ar + 32 * i) * AS_STRIDE + ak) = tf32r4(ra[i]);
        if (NT) {
#pragma unroll
            for (int i = 0; i < 4; i++)
                *(uint4*)(Bd + (ar + 32 * i) * BS_NT_STRIDE + ak) = tf32r4(rb[i]);
        } else {
#pragma unroll
            for (int i = 0; i < 4; i++)
                *(uint4*)(Bd + bkr * BS_NN_STRIDE + bnc + 32 * i) = tf32r4(rb[i]);
        }
    };

    ldg(0);

    for (int c = 0; c < nchunks; ++c) {
        const int s = c & 1;
        sts(s);
        __syncthreads();
        if (c + 1 < nchunks) ldg((c + 1) << 4);

        const uint32_t* Asb = As + s * AS_ELEMS;
        const uint32_t* Bsb = Bs + s * BS_ELEMS;

#pragma unroll
        for (int ks = 0; ks < 2; ++ks) {
            const int k8 = ks * 8;
            uint32_t af[4][4];
#pragma unroll
            for (int mt = 0; mt < 4; mt++) {
                const int r  = wm + mt * 16 + g4;
                const int cc = k8 + l4;
                af[mt][0] = Asb[r * AS_STRIDE + cc];
                af[mt][1] = Asb[(r + 8) * AS_STRIDE + cc];
                af[mt][2] = Asb[r * AS_STRIDE + cc + 4];
                af[mt][3] = Asb[(r + 8) * AS_STRIDE + cc + 4];
            }
            uint32_t bf[8][2];
#pragma unroll
            for (int nt = 0; nt < 8; nt++) {
                const int col = wn + nt * 8 + g4;
                const int kk  = k8 + l4;
                if (NT) {
                    bf[nt][0] = Bsb[col * BS_NT_STRIDE + kk];
                    bf[nt][1] = Bsb[col * BS_NT_STRIDE + kk + 4];
                } else {
                    bf[nt][0] = Bsb[kk * BS_NN_STRIDE + col];
                    bf[nt][1] = Bsb[(kk + 4) * BS_NN_STRIDE + col];
                }
            }
#pragma unroll
            for (int mt = 0; mt < 4; mt++)
#pragma unroll
                for (int nt = 0; nt < 8; nt++)
                    mma_tf32(acc[mt][nt][0], acc[mt][nt][1], acc[mt][nt][2], acc[mt][nt][3],
                             af[mt][0], af[mt][1], af[mt][2], af[mt][3],
                             bf[nt][0], bf[nt][1]);
        }
        __syncthreads();
    }

    // --- epilogue ---
#pragma unroll
    for (int mt = 0; mt < 4; mt++) {
        const int r = m0 + wm + mt * 16 + g4;
#pragma unroll
        for (int nt = 0; nt < 8; nt++) {
            const int col = n0 + wn + nt * 8 + 2 * l4;
            float bx = 0.f, by = 0.f;
            if (bias) { bx = bias[col]; by = bias[col + 1]; }
            float v0 = acc[mt][nt][0] + bx;
            float v1 = acc[mt][nt][1] + by;
            float v2 = acc[mt][nt][2] + bx;
            float v3 = acc[mt][nt][3] + by;
            if (relu) {
                v0 = fmaxf(v0, 0.f); v1 = fmaxf(v1, 0.f);
                v2 = fmaxf(v2, 0.f); v3 = fmaxf(v3, 0.f);
            }
            *(float2*)(Cout + (size_t)r * N + col)       = make_float2(v0, v1);
            *(float2*)(Cout + (size_t)(r + 8) * N + col) = make_float2(v2, v3);
        }
    }
}

// ---------------------------------------------------------------------------
// Kernels
// ---------------------------------------------------------------------------

// z=0 -> q, z=1 -> k, z=2 -> v : relu(h @ W^T + b)  M=32768, N=512, K=256
__global__ void __launch_bounds__(128, 2)
qkv_kernel(const float* __restrict__ h,
           const float* __restrict__ Wq, const float* __restrict__ bq,
           const float* __restrict__ Wk, const float* __restrict__ bk,
           const float* __restrict__ Wv, const float* __restrict__ bv)
{
    const float* W; const float* bia; float* out;
    if (blockIdx.z == 0)      { W = Wq; bia = bq; out = g_q; }
    else if (blockIdx.z == 1) { W = Wk; bia = bk; out = g_k; }
    else                      { W = Wv; bia = bv; out = g_v; }
    mma_gemm_body<true>(h, W, bia, out, HID, DIN,
                        blockIdx.y * BM, blockIdx.x * BN, true);
}

// S[b] = Q[b] @ K[b]^T : M=N=1024, K=512 per batch
__global__ void __launch_bounds__(128, 2)
scores_kernel()
{
    const int b = blockIdx.z;
    const float* Q = g_q + (size_t)b * SEQ * HID;
    const float* K = g_k + (size_t)b * SEQ * HID;
    float* S = g_s + (size_t)b * SEQ * SEQ;
    mma_gemm_body<true>(Q, K, nullptr, S, SEQ, HID,
                        blockIdx.y * BM, blockIdx.x * BN, false);
}

// Row softmax over g_s, one block (256 threads) per row of 1024
__global__ void softmax_kernel()
{
    __shared__ float red[8];
    float* row = g_s + (size_t)blockIdx.x * SEQ;
    const int t = threadIdx.x;
    const int lane = t & 31, warp = t >> 5;

    float4 v = *(const float4*)(row + t * 4);
    float m = fmaxf(fmaxf(v.x, v.y), fmaxf(v.z, v.w));
#pragma unroll
    for (int o = 16; o > 0; o >>= 1) m = fmaxf(m, __shfl_xor_sync(0xffffffffu, m, o));
    if (lane == 0) red[warp] = m;
    __syncthreads();
    if (warp == 0) {
        float mm = red[lane & 7];
#pragma unroll
        for (int o = 4; o > 0; o >>= 1) mm = fmaxf(mm, __shfl_xor_sync(0xffffffffu, mm, o));
        if (lane == 0) red[0] = mm;
    }
    __syncthreads();
    m = red[0];
    __syncthreads();

    v.x = expf(v.x - m); v.y = expf(v.y - m);
    v.z = expf(v.z - m); v.w = expf(v.w - m);
    float s = v.x + v.y + v.z + v.w;
#pragma unroll
    for (int o = 16; o > 0; o >>= 1) s += __shfl_xor_sync(0xffffffffu, s, o);
    if (lane == 0) red[warp] = s;
    __syncthreads();
    if (warp == 0) {
        float ss = red[lane & 7];
#pragma unroll
        for (int o = 4; o > 0; o >>= 1) ss += __shfl_xor_sync(0xffffffffu, ss, o);
        if (lane == 0) red[0] = ss;
    }
    __syncthreads();
    float inv = 1.0f / red[0];
    v.x *= inv; v.y *= inv; v.z *= inv; v.w *= inv;
    *(float4*)(row + t * 4) = v;
}

// O[b] = P[b] @ V[b] : M=1024, N=512, K=1024 per batch (NN)
__global__ void __launch_bounds__(128, 2)
pv_kernel()
{
    const int b = blockIdx.z;
    const float* P = g_s + (size_t)b * SEQ * SEQ;
    const float* V = g_v + (size_t)b * SEQ * HID;
    float* O = g_o + (size_t)b * SEQ * HID;
    mma_gemm_body<false>(P, V, nullptr, O, HID, SEQ,
                         blockIdx.y * BM, blockIdx.x * BN, false);
}

// out = relu(O @ Wo^T + bo) : M=32768, N=256, K=512
__global__ void __launch_bounds__(128, 2)
outproj_kernel(const float* __restrict__ Wo,
               const float* __restrict__ bo,
               float* __restrict__ out)
{
    mma_gemm_body<true>(g_o, Wo, bo, out, DIN, HID,
                        blockIdx.y * BM, blockIdx.x * BN, true);
}

// ---------------------------------------------------------------------------
// Launch
// ---------------------------------------------------------------------------
extern "C" void kernel_launch(void* const* d_in, const int* in_sizes, int n_in,
                              void* d_out, int out_size)
{
    const float* h  = (const float*)d_in[0];
    const float* Wv = (const float*)d_in[1];
    const float* bv = (const float*)d_in[2];
    const float* Wk = (const float*)d_in[3];
    const float* bk = (const float*)d_in[4];
    const float* Wq = (const float*)d_in[5];
    const float* bq = (const float*)d_in[6];
    const float* Wo = (const float*)d_in[7];
    const float* bo = (const float*)d_in[8];
    float* out = (float*)d_out;

    dim3 gQKV(HID / BN, MTOT / BM, 3);
    qkv_kernel<<<gQKV, 128>>>(h, Wq, bq, Wk, bk, Wv, bv);

    dim3 gS(SEQ / BN, SEQ / BM, BATCH);
    scores_kernel<<<gS, 128>>>();

    softmax_kernel<<<BATCH * SEQ, 256>>>();

    dim3 gPV(HID / BN, SEQ / BM, BATCH);
    pv_kernel<<<gPV, 128>>>();

    dim3 gO(DIN / BN, MTOT / BM, 1);
    outproj_kernel<<<gO, 128>>>(Wo, bo, out);
}

// round 11
// speedup vs baseline: 7.0312x; 1.1639x over previous
#include <cuda_runtime.h>
#include <cstddef>
#include <cstdint>

// Problem dims (fixed by the reference)
#define BATCH 32
#define SEQ   1024
#define DIN   256
#define HID   512
#define MTOT  (BATCH * SEQ)   // 32768

// GEMM tiling: block 128x128, BK=32, 4 warps (2x2), warp tile 64x64
#define BM 128
#define BN 128
#define BK 32
#define AST 36            // A smem row stride (floats): bank (4*g4+l4)%32 distinct
#define BNT_ST 36         // NT-B same layout as A
#define BNN_ST 136        // NN-B: bank (8*l4+g4)%32 distinct
#define ASZ (BM * AST)    // 4608 u32 per stage
#define BSZ 4608          // max(128*36, 32*136=4352)
#define SMEM_DYN ((2 * ASZ + 2 * BSZ) * 4)   // 73728 bytes

// Scratch in __device__ globals (allocation-free rule)
__device__ float g_q[(size_t)BATCH * SEQ * HID];
__device__ float g_k[(size_t)BATCH * SEQ * HID];
__device__ float g_v[(size_t)BATCH * SEQ * HID];
__device__ float g_s[(size_t)BATCH * SEQ * SEQ];
__device__ float g_o[(size_t)BATCH * SEQ * HID];
// tf32-pre-rounded copies of external inputs
__device__ float g_ht[(size_t)MTOT * DIN];
__device__ float g_wq[(size_t)HID * DIN];
__device__ float g_wk[(size_t)HID * DIN];
__device__ float g_wv[(size_t)HID * DIN];
__device__ float g_wo[(size_t)DIN * HID];

// ---------------------------------------------------------------------------
// PTX helpers
// ---------------------------------------------------------------------------
__device__ __forceinline__ void cp16(uint32_t* s, const float* g) {
    uint32_t sa = (uint32_t)__cvta_generic_to_shared(s);
    asm volatile("cp.async.cg.shared.global [%0], [%1], 16;\n" :: "r"(sa), "l"(g));
}
__device__ __forceinline__ void cp_commit() { asm volatile("cp.async.commit_group;\n"); }
__device__ __forceinline__ void cp_wait1()  { asm volatile("cp.async.wait_group 1;\n"); }
__device__ __forceinline__ void cp_wait0()  { asm volatile("cp.async.wait_group 0;\n"); }
__device__ __forceinline__ uint32_t tf32r(float x) {
    uint32_t u;
    asm("cvt.rna.tf32.f32 %0, %1;\n" : "=r"(u) : "f"(x));
    return u;
}
__device__ __forceinline__ float tf32f(float x) { return __uint_as_float(tf32r(x)); }
__device__ __forceinline__ void mma_tf32(float& c0, float& c1, float& c2, float& c3,
                                         uint32_t a0, uint32_t a1, uint32_t a2, uint32_t a3,
                                         uint32_t b0, uint32_t b1) {
    asm volatile(
        "mma.sync.aligned.m16n8k8.row.col.f32.tf32.tf32.f32 "
        "{%0,%1,%2,%3}, {%4,%5,%6,%7}, {%8,%9}, {%0,%1,%2,%3};\n"
        : "+f"(c0), "+f"(c1), "+f"(c2), "+f"(c3)
        : "r"(a0), "r"(a1), "r"(a2), "r"(a3), "r"(b0), "r"(b1));
}

// ---------------------------------------------------------------------------
// Tensor-core GEMM body (register MMA, tf32). Operands are ALREADY tf32-
// rounded fp32 in gmem, so staging is pure cp.async (no cvt on the path).
//   NT=true : C[M,N] = act(A[M,K] * B[N,K]^T + bias)
//   NT=false: C[M,N] = A[M,K] * B[K,N]          (bias must be nullptr)
//   ROUND   : round outputs to tf32 on store (producer-side rounding)
// ---------------------------------------------------------------------------
template<bool NT, bool ROUND>
__device__ __forceinline__ void mma_gemm_body(
    const float* __restrict__ A, const float* __restrict__ B,
    const float* __restrict__ bias, float* __restrict__ Cout,
    int N, int K, int m0, int n0, bool relu)
{
    extern __shared__ uint32_t sm[];
    uint32_t* Asm = sm;                  // 2 stages x ASZ
    uint32_t* Bsm = sm + 2 * ASZ;        // 2 stages x BSZ

    const int t    = threadIdx.x;        // 0..127
    const int lane = t & 31;
    const int warp = t >> 5;             // 0..3
    const int wm   = (warp >> 1) * 64;   // 0,64
    const int wn   = (warp & 1) * 64;    // 0,64
    const int g4   = lane >> 2;          // 0..7
    const int l4   = lane & 3;           // 0..3

    float acc[4][8][4];
#pragma unroll
    for (int mt = 0; mt < 4; mt++)
#pragma unroll
        for (int nt = 0; nt < 8; nt++)
#pragma unroll
            for (int i = 0; i < 4; i++) acc[mt][nt][i] = 0.f;

    const int nchunks = K >> 5;

    auto stage = [&](int s, int kt) {
        uint32_t* Ad = Asm + s * ASZ;
        uint32_t* Bd = Bsm + s * BSZ;
        // A tile: 128 rows x 32 floats = 1024 16B segs, 8 per thread
#pragma unroll
        for (int i = 0; i < 8; i++) {
            const int seg = t + 128 * i;
            const int row = seg >> 3, ss = (seg & 7) << 2;
            cp16(Ad + row * AST + ss, A + (size_t)(m0 + row) * K + kt + ss);
        }
        if (NT) {
#pragma unroll
            for (int i = 0; i < 8; i++) {
                const int seg = t + 128 * i;
                const int row = seg >> 3, ss = (seg & 7) << 2;
                cp16(Bd + row * BNT_ST + ss, B + (size_t)(n0 + row) * K + kt + ss);
            }
        } else {
            // B tile: 32 k-rows x 128 floats = 1024 segs, 8 per thread
#pragma unroll
            for (int i = 0; i < 8; i++) {
                const int seg = t + 128 * i;
                const int kr = seg >> 5, ss = (seg & 31) << 2;
                cp16(Bd + kr * BNN_ST + ss, B + (size_t)(kt + kr) * N + n0 + ss);
            }
        }
    };

    stage(0, 0);
    cp_commit();

    for (int c = 0; c < nchunks; ++c) {
        const int s = c & 1;
        if (c + 1 < nchunks) {
            stage(s ^ 1, (c + 1) << 5);
            cp_commit();
            cp_wait1();
        } else {
            cp_wait0();
        }
        __syncthreads();

        const uint32_t* Asb = Asm + s * ASZ;
        const uint32_t* Bsb = Bsm + s * BSZ;

#pragma unroll
        for (int ks = 0; ks < 4; ++ks) {
            const int k8 = ks * 8;
            uint32_t af[4][4];
#pragma unroll
            for (int mt = 0; mt < 4; mt++) {
                const int r  = wm + mt * 16 + g4;
                const int cc = k8 + l4;
                af[mt][0] = Asb[r * AST + cc];
                af[mt][1] = Asb[(r + 8) * AST + cc];
                af[mt][2] = Asb[r * AST + cc + 4];
                af[mt][3] = Asb[(r + 8) * AST + cc + 4];
            }
            uint32_t bf[8][2];
#pragma unroll
            for (int nt = 0; nt < 8; nt++) {
                const int col = wn + nt * 8 + g4;
                const int kk  = k8 + l4;
                if (NT) {
                    bf[nt][0] = Bsb[col * BNT_ST + kk];
                    bf[nt][1] = Bsb[col * BNT_ST + kk + 4];
                } else {
                    bf[nt][0] = Bsb[kk * BNN_ST + col];
                    bf[nt][1] = Bsb[(kk + 4) * BNN_ST + col];
                }
            }
#pragma unroll
            for (int mt = 0; mt < 4; mt++)
#pragma unroll
                for (int nt = 0; nt < 8; nt++)
                    mma_tf32(acc[mt][nt][0], acc[mt][nt][1], acc[mt][nt][2], acc[mt][nt][3],
                             af[mt][0], af[mt][1], af[mt][2], af[mt][3],
                             bf[nt][0], bf[nt][1]);
        }
        __syncthreads();
    }

    // --- epilogue ---
#pragma unroll
    for (int mt = 0; mt < 4; mt++) {
        const int r = m0 + wm + mt * 16 + g4;
#pragma unroll
        for (int nt = 0; nt < 8; nt++) {
            const int col = n0 + wn + nt * 8 + 2 * l4;
            float bx = 0.f, by = 0.f;
            if (bias) { bx = bias[col]; by = bias[col + 1]; }
            float v0 = acc[mt][nt][0] + bx;
            float v1 = acc[mt][nt][1] + by;
            float v2 = acc[mt][nt][2] + bx;
            float v3 = acc[mt][nt][3] + by;
            if (relu) {
                v0 = fmaxf(v0, 0.f); v1 = fmaxf(v1, 0.f);
                v2 = fmaxf(v2, 0.f); v3 = fmaxf(v3, 0.f);
            }
            if (ROUND) {
                v0 = tf32f(v0); v1 = tf32f(v1);
                v2 = tf32f(v2); v3 = tf32f(v3);
            }
            *(float2*)(Cout + (size_t)r * N + col)       = make_float2(v0, v1);
            *(float2*)(Cout + (size_t)(r + 8) * N + col) = make_float2(v2, v3);
        }
    }
}

// ---------------------------------------------------------------------------
// Kernels
// ---------------------------------------------------------------------------

// Pre-round fp32 -> tf32-in-fp32 (elementwise, 4 per thread)
__global__ void round_kernel(const float* __restrict__ in, float* __restrict__ out, int n)
{
    const int i = (blockIdx.x * blockDim.x + threadIdx.x) * 4;
    if (i < n) {
        float4 v = *(const float4*)(in + i);
        v.x = tf32f(v.x); v.y = tf32f(v.y); v.z = tf32f(v.z); v.w = tf32f(v.w);
        *(float4*)(out + i) = v;
    }
}

// z=0 -> q, z=1 -> k, z=2 -> v : relu(h @ W^T + b)  M=32768, N=512, K=256
__global__ void __launch_bounds__(128, 2)
qkv_kernel(const float* __restrict__ bq, const float* __restrict__ bk,
           const float* __restrict__ bv)
{
    const float* W; const float* bia; float* out;
    if (blockIdx.z == 0)      { W = g_wq; bia = bq; out = g_q; }
    else if (blockIdx.z == 1) { W = g_wk; bia = bk; out = g_k; }
    else                      { W = g_wv; bia = bv; out = g_v; }
    mma_gemm_body<true, true>(g_ht, W, bia, out, HID, DIN,
                              blockIdx.y * BM, blockIdx.x * BN, true);
}

// S[b] = Q[b] @ K[b]^T : M=N=1024, K=512 per batch  (S stays fp32)
__global__ void __launch_bounds__(128, 2)
scores_kernel()
{
    const int b = blockIdx.z;
    const float* Q = g_q + (size_t)b * SEQ * HID;
    const float* K = g_k + (size_t)b * SEQ * HID;
    float* S = g_s + (size_t)b * SEQ * SEQ;
    mma_gemm_body<true, false>(Q, K, nullptr, S, SEQ, HID,
                               blockIdx.y * BM, blockIdx.x * BN, false);
}

// Row softmax over g_s; writes P tf32-rounded (producer-side rounding)
__global__ void softmax_kernel()
{
    __shared__ float red[8];
    float* row = g_s + (size_t)blockIdx.x * SEQ;
    const int t = threadIdx.x;
    const int lane = t & 31, warp = t >> 5;

    float4 v = *(const float4*)(row + t * 4);
    float m = fmaxf(fmaxf(v.x, v.y), fmaxf(v.z, v.w));
#pragma unroll
    for (int o = 16; o > 0; o >>= 1) m = fmaxf(m, __shfl_xor_sync(0xffffffffu, m, o));
    if (lane == 0) red[warp] = m;
    __syncthreads();
    if (warp == 0) {
        float mm = red[lane & 7];
#pragma unroll
        for (int o = 4; o > 0; o >>= 1) mm = fmaxf(mm, __shfl_xor_sync(0xffffffffu, mm, o));
        if (lane == 0) red[0] = mm;
    }
    __syncthreads();
    m = red[0];
    __syncthreads();

    v.x = expf(v.x - m); v.y = expf(v.y - m);
    v.z = expf(v.z - m); v.w = expf(v.w - m);
    float s = v.x + v.y + v.z + v.w;
#pragma unroll
    for (int o = 16; o > 0; o >>= 1) s += __shfl_xor_sync(0xffffffffu, s, o);
    if (lane == 0) red[warp] = s;
    __syncthreads();
    if (warp == 0) {
        float ss = red[lane & 7];
#pragma unroll
        for (int o = 4; o > 0; o >>= 1) ss += __shfl_xor_sync(0xffffffffu, ss, o);
        if (lane == 0) red[0] = ss;
    }
    __syncthreads();
    float inv = 1.0f / red[0];
    v.x = tf32f(v.x * inv); v.y = tf32f(v.y * inv);
    v.z = tf32f(v.z * inv); v.w = tf32f(v.w * inv);
    *(float4*)(row + t * 4) = v;
}

// O[b] = P[b] @ V[b] : M=1024, N=512, K=1024 per batch (NN); O tf32-rounded
__global__ void __launch_bounds__(128, 2)
pv_kernel()
{
    const int b = blockIdx.z;
    const float* P = g_s + (size_t)b * SEQ * SEQ;
    const float* V = g_v + (size_t)b * SEQ * HID;
    float* O = g_o + (size_t)b * SEQ * HID;
    mma_gemm_body<false, true>(P, V, nullptr, O, HID, SEQ,
                               blockIdx.y * BM, blockIdx.x * BN, false);
}

// out = relu(O @ Wo^T + bo) : M=32768, N=256, K=512  (final fp32, no rounding)
__global__ void __launch_bounds__(128, 2)
outproj_kernel(const float* __restrict__ bo, float* __restrict__ out)
{
    mma_gemm_body<true, false>(g_o, g_wo, bo, out, DIN, HID,
                               blockIdx.y * BM, blockIdx.x * BN, true);
}

// ---------------------------------------------------------------------------
// Launch
// ---------------------------------------------------------------------------
extern "C" void kernel_launch(void* const* d_in, const int* in_sizes, int n_in,
                              void* d_out, int out_size)
{
    const float* h  = (const float*)d_in[0];
    const float* Wv = (const float*)d_in[1];
    const float* bv = (const float*)d_in[2];
    const float* Wk = (const float*)d_in[3];
    const float* bk = (const float*)d_in[4];
    const float* Wq = (const float*)d_in[5];
    const float* bq = (const float*)d_in[6];
    const float* Wo = (const float*)d_in[7];
    const float* bo = (const float*)d_in[8];
    float* out = (float*)d_out;

    // Opt-in to 72KB dynamic smem (persistent attribute; harmless to repeat)
    static bool attr_done = false;
    if (!attr_done) {
        cudaFuncSetAttribute(qkv_kernel,     cudaFuncAttributeMaxDynamicSharedMemorySize, SMEM_DYN);
        cudaFuncSetAttribute(scores_kernel,  cudaFuncAttributeMaxDynamicSharedMemorySize, SMEM_DYN);
        cudaFuncSetAttribute(pv_kernel,      cudaFuncAttributeMaxDynamicSharedMemorySize, SMEM_DYN);
        cudaFuncSetAttribute(outproj_kernel, cudaFuncAttributeMaxDynamicSharedMemorySize, SMEM_DYN);
        attr_done = true;
    }

    // Resolve scratch addresses (host-side; cheap, capture-safe)
    float *ht, *wq, *wk, *wv, *wo;
    cudaGetSymbolAddress((void**)&ht, g_ht);
    cudaGetSymbolAddress((void**)&wq, g_wq);
    cudaGetSymbolAddress((void**)&wk, g_wk);
    cudaGetSymbolAddress((void**)&wv, g_wv);
    cudaGetSymbolAddress((void**)&wo, g_wo);

    // Pre-round inputs to tf32 (producer-side rounding)
    round_kernel<<<(MTOT * DIN) / 1024, 256>>>(h, ht, MTOT * DIN);
    round_kernel<<<(HID * DIN) / 1024, 256>>>(Wq, wq, HID * DIN);
    round_kernel<<<(HID * DIN) / 1024, 256>>>(Wk, wk, HID * DIN);
    round_kernel<<<(HID * DIN) / 1024, 256>>>(Wv, wv, HID * DIN);
    round_kernel<<<(DIN * HID) / 1024, 256>>>(Wo, wo, DIN * HID);

    dim3 gQKV(HID / BN, MTOT / BM, 3);
    qkv_kernel<<<gQKV, 128, SMEM_DYN>>>(bq, bk, bv);

    dim3 gS(SEQ / BN, SEQ / BM, BATCH);
    scores_kernel<<<gS, 128, SMEM_DYN>>>();

    softmax_kernel<<<BATCH * SEQ, 256>>>();

    dim3 gPV(HID / BN, SEQ / BM, BATCH);
    pv_kernel<<<gPV, 128, SMEM_DYN>>>();

    dim3 gO(DIN / BN, MTOT / BM, 1);
    outproj_kernel<<<gO, 128, SMEM_DYN>>>(bo, out);
}

// round 12
// speedup vs baseline: 11.4938x; 1.6347x over previous
#include <cuda_runtime.h>
#include <cuda_fp16.h>
#include <cstddef>
#include <cstdint>

// Problem dims (fixed by the reference)
#define BATCH 32
#define SEQ   1024
#define DIN   256
#define HID   512
#define MTOT  (BATCH * SEQ)   // 32768

// GEMM tiling: block 128x128, BK=64 (fp16), 4 warps (2x2), warp tile 64x64
#define BM 128
#define BN 128
#define BK 64
#define SHH 72                 // smem row stride in halfs (144 B, 16B-aligned)
#define SH2 36                 // row stride in half2 (bank stride 36%32=4 -> CF)
#define TILE_BYTES (BM * SHH * 2)          // 18432
#define SMEM_DYN (4 * TILE_BYTES)          // 73728 (A,B x 2 stages)

// Scratch in __device__ globals (allocation-free rule). Halfs as u16.
__device__ unsigned short g_h [(size_t)MTOT * DIN];
__device__ unsigned short g_wq[(size_t)HID * DIN];
__device__ unsigned short g_wk[(size_t)HID * DIN];
__device__ unsigned short g_wv[(size_t)HID * DIN];
__device__ unsigned short g_wo[(size_t)DIN * HID];
__device__ unsigned short g_q [(size_t)BATCH * SEQ * HID];
__device__ unsigned short g_k [(size_t)BATCH * SEQ * HID];
__device__ unsigned short g_v [(size_t)BATCH * SEQ * HID];
__device__ unsigned short g_vt[(size_t)BATCH * SEQ * HID];   // [b][hid][seq]
__device__ unsigned short g_o [(size_t)BATCH * SEQ * HID];
__device__ unsigned short g_p [(size_t)BATCH * SEQ * SEQ];   // softmax(P), fp16
__device__ float          g_s [(size_t)BATCH * SEQ * SEQ];   // logits, fp32

// ---------------------------------------------------------------------------
// PTX helpers
// ---------------------------------------------------------------------------
__device__ __forceinline__ void cp16(void* s, const void* g) {
    uint32_t sa = (uint32_t)__cvta_generic_to_shared(s);
    asm volatile("cp.async.cg.shared.global [%0], [%1], 16;\n" :: "r"(sa), "l"(g));
}
__device__ __forceinline__ void cp_commit() { asm volatile("cp.async.commit_group;\n"); }
__device__ __forceinline__ void cp_wait1()  { asm volatile("cp.async.wait_group 1;\n"); }
__device__ __forceinline__ void cp_wait0()  { asm volatile("cp.async.wait_group 0;\n"); }
__device__ __forceinline__ void mma_f16(float& c0, float& c1, float& c2, float& c3,
                                        uint32_t a0, uint32_t a1, uint32_t a2, uint32_t a3,
                                        uint32_t b0, uint32_t b1) {
    asm volatile(
        "mma.sync.aligned.m16n8k16.row.col.f32.f16.f16.f32 "
        "{%0,%1,%2,%3}, {%4,%5,%6,%7}, {%8,%9}, {%0,%1,%2,%3};\n"
        : "+f"(c0), "+f"(c1), "+f"(c2), "+f"(c3)
        : "r"(a0), "r"(a1), "r"(a2), "r"(a3), "r"(b0), "r"(b1));
}

// ---------------------------------------------------------------------------
// fp16 NT GEMM body: C[M,N] = act(A[M,K] * B[N,K]^T + bias)
// A, B fp16 K-major. acc fp32. OUTH: store half, else fp32.
// Double-buffered cp.async staging, BK=64 (4 x k16 steps per chunk).
// ---------------------------------------------------------------------------
template<bool OUTH>
__device__ __forceinline__ void gemm_nt_f16(
    const unsigned short* __restrict__ A, const unsigned short* __restrict__ B,
    const float* __restrict__ bias, void* __restrict__ Cout,
    int N, int K, int m0, int n0, bool relu)
{
    extern __shared__ char sm[];
    // A stages at 0, TILE_BYTES; B stages at 2*TILE_BYTES, 3*TILE_BYTES
    const int t    = threadIdx.x;        // 0..127
    const int lane = t & 31;
    const int warp = t >> 5;             // 0..3
    const int wm   = (warp >> 1) * 64;   // 0,64
    const int wn   = (warp & 1) * 64;    // 0,64
    const int g4   = lane >> 2;          // 0..7
    const int l4   = lane & 3;           // 0..3

    float acc[4][8][4];
#pragma unroll
    for (int mt = 0; mt < 4; mt++)
#pragma unroll
        for (int nt = 0; nt < 8; nt++)
#pragma unroll
            for (int i = 0; i < 4; i++) acc[mt][nt][i] = 0.f;

    const int nchunks = K >> 6;

    auto stage = [&](int s, int kt) {
        char* Ad = sm + s * TILE_BYTES;
        char* Bd = sm + 2 * TILE_BYTES + s * TILE_BYTES;
        // tile = 128 rows x 64 halfs = 128B/row = 8 x 16B segs; 1024 segs total
#pragma unroll
        for (int i = 0; i < 8; i++) {
            const int seg = t + 128 * i;
            const int row = seg >> 3, sg = seg & 7;
            cp16(Ad + row * 144 + sg * 16, A + (size_t)(m0 + row) * K + kt + sg * 8);
        }
#pragma unroll
        for (int i = 0; i < 8; i++) {
            const int seg = t + 128 * i;
            const int row = seg >> 3, sg = seg & 7;
            cp16(Bd + row * 144 + sg * 16, B + (size_t)(n0 + row) * K + kt + sg * 8);
        }
    };

    stage(0, 0);
    cp_commit();

    for (int c = 0; c < nchunks; ++c) {
        const int s = c & 1;
        if (c + 1 < nchunks) {
            stage(s ^ 1, (c + 1) << 6);
            cp_commit();
            cp_wait1();
        } else {
            cp_wait0();
        }
        __syncthreads();

        const uint32_t* Asb = (const uint32_t*)(sm + s * TILE_BYTES);
        const uint32_t* Bsb = (const uint32_t*)(sm + 2 * TILE_BYTES + s * TILE_BYTES);

#pragma unroll
        for (int ks = 0; ks < 4; ++ks) {
            const int kb = ks * 8;   // half2 offset of this k16 group
            uint32_t af[4][4];
#pragma unroll
            for (int mt = 0; mt < 4; mt++) {
                const int r = wm + mt * 16 + g4;
                af[mt][0] = Asb[r * SH2 + kb + l4];
                af[mt][1] = Asb[(r + 8) * SH2 + kb + l4];
                af[mt][2] = Asb[r * SH2 + kb + 4 + l4];
                af[mt][3] = Asb[(r + 8) * SH2 + kb + 4 + l4];
            }
            uint32_t bf[8][2];
#pragma unroll
            for (int nt = 0; nt < 8; nt++) {
                const int col = wn + nt * 8 + g4;
                bf[nt][0] = Bsb[col * SH2 + kb + l4];
                bf[nt][1] = Bsb[col * SH2 + kb + 4 + l4];
            }
#pragma unroll
            for (int mt = 0; mt < 4; mt++)
#pragma unroll
                for (int nt = 0; nt < 8; nt++)
                    mma_f16(acc[mt][nt][0], acc[mt][nt][1], acc[mt][nt][2], acc[mt][nt][3],
                            af[mt][0], af[mt][1], af[mt][2], af[mt][3],
                            bf[nt][0], bf[nt][1]);
        }
        __syncthreads();
    }

    // --- epilogue ---
#pragma unroll
    for (int mt = 0; mt < 4; mt++) {
        const int r = m0 + wm + mt * 16 + g4;
#pragma unroll
        for (int nt = 0; nt < 8; nt++) {
            const int col = n0 + wn + nt * 8 + 2 * l4;
            float bx = 0.f, by = 0.f;
            if (bias) { bx = bias[col]; by = bias[col + 1]; }
            float v0 = acc[mt][nt][0] + bx;
            float v1 = acc[mt][nt][1] + by;
            float v2 = acc[mt][nt][2] + bx;
            float v3 = acc[mt][nt][3] + by;
            if (relu) {
                v0 = fmaxf(v0, 0.f); v1 = fmaxf(v1, 0.f);
                v2 = fmaxf(v2, 0.f); v3 = fmaxf(v3, 0.f);
            }
            if (OUTH) {
                __half2* o = (__half2*)((unsigned short*)Cout + (size_t)r * N + col);
                *o = __floats2half2_rn(v0, v1);
                __half2* o2 = (__half2*)((unsigned short*)Cout + (size_t)(r + 8) * N + col);
                *o2 = __floats2half2_rn(v2, v3);
            } else {
                *(float2*)((float*)Cout + (size_t)r * N + col)       = make_float2(v0, v1);
                *(float2*)((float*)Cout + (size_t)(r + 8) * N + col) = make_float2(v2, v3);
            }
        }
    }
}

// ---------------------------------------------------------------------------
// Kernels
// ---------------------------------------------------------------------------

// fp32 -> fp16 convert (4 elems/thread)
__global__ void cvt_half_kernel(const float* __restrict__ in,
                                unsigned short* __restrict__ out, int n)
{
    const int i = (blockIdx.x * blockDim.x + threadIdx.x) * 4;
    if (i < n) {
        float4 v = *(const float4*)(in + i);
        __half2* o = (__half2*)(out + i);
        o[0] = __floats2half2_rn(v.x, v.y);
        o[1] = __floats2half2_rn(v.z, v.w);
    }
}

// z=0 -> q, z=1 -> k, z=2 -> v : relu(h @ W^T + b)  M=32768, N=512, K=256
__global__ void __launch_bounds__(128, 2)
qkv_kernel(const float* __restrict__ bq, const float* __restrict__ bk,
           const float* __restrict__ bv)
{
    const unsigned short* W; const float* bia; unsigned short* out;
    if (blockIdx.z == 0)      { W = g_wq; bia = bq; out = g_q; }
    else if (blockIdx.z == 1) { W = g_wk; bia = bk; out = g_k; }
    else                      { W = g_wv; bia = bv; out = g_v; }
    gemm_nt_f16<true>(g_h, W, bia, out, HID, DIN,
                      blockIdx.y * BM, blockIdx.x * BN, true);
}

// V[b][s][h] -> Vt[b][h][s]  (32x32 fp16 tiles)
__global__ void transpose_kernel()
{
    __shared__ unsigned short tile[32][34];
    const int b  = blockIdx.z;
    const int h0 = blockIdx.x * 32;
    const int s0 = blockIdx.y * 32;
    const int tx = threadIdx.x, ty = threadIdx.y;  // 32 x 8
    const unsigned short* V = g_v + (size_t)b * SEQ * HID;
    unsigned short* Vt = g_vt + (size_t)b * SEQ * HID;
#pragma unroll
    for (int i = 0; i < 4; i++)
        tile[ty + 8 * i][tx] = V[(size_t)(s0 + ty + 8 * i) * HID + h0 + tx];
    __syncthreads();
#pragma unroll
    for (int i = 0; i < 4; i++)
        Vt[(size_t)(h0 + ty + 8 * i) * SEQ + s0 + tx] = tile[tx][ty + 8 * i];
}

// S[b] = Q[b] @ K[b]^T : M=N=1024, K=512 per batch (fp32 logits out)
__global__ void __launch_bounds__(128, 2)
scores_kernel()
{
    const int b = blockIdx.z;
    const unsigned short* Q = g_q + (size_t)b * SEQ * HID;
    const unsigned short* K = g_k + (size_t)b * SEQ * HID;
    float* S = g_s + (size_t)b * SEQ * SEQ;
    gemm_nt_f16<false>(Q, K, nullptr, S, SEQ, HID,
                       blockIdx.y * BM, blockIdx.x * BN, false);
}

// Row softmax: fp32 logits in g_s -> fp16 probabilities in g_p
__global__ void softmax_kernel()
{
    __shared__ float red[8];
    const float* row = g_s + (size_t)blockIdx.x * SEQ;
    unsigned short* prow = g_p + (size_t)blockIdx.x * SEQ;
    const int t = threadIdx.x;
    const int lane = t & 31, warp = t >> 5;

    float4 v = *(const float4*)(row + t * 4);
    float m = fmaxf(fmaxf(v.x, v.y), fmaxf(v.z, v.w));
#pragma unroll
    for (int o = 16; o > 0; o >>= 1) m = fmaxf(m, __shfl_xor_sync(0xffffffffu, m, o));
    if (lane == 0) red[warp] = m;
    __syncthreads();
    if (warp == 0) {
        float mm = red[lane & 7];
#pragma unroll
        for (int o = 4; o > 0; o >>= 1) mm = fmaxf(mm, __shfl_xor_sync(0xffffffffu, mm, o));
        if (lane == 0) red[0] = mm;
    }
    __syncthreads();
    m = red[0];
    __syncthreads();

    v.x = expf(v.x - m); v.y = expf(v.y - m);
    v.z = expf(v.z - m); v.w = expf(v.w - m);
    float s = v.x + v.y + v.z + v.w;
#pragma unroll
    for (int o = 16; o > 0; o >>= 1) s += __shfl_xor_sync(0xffffffffu, s, o);
    if (lane == 0) red[warp] = s;
    __syncthreads();
    if (warp == 0) {
        float ss = red[lane & 7];
#pragma unroll
        for (int o = 4; o > 0; o >>= 1) ss += __shfl_xor_sync(0xffffffffu, ss, o);
        if (lane == 0) red[0] = ss;
    }
    __syncthreads();
    float inv = 1.0f / red[0];
    __half2* o = (__half2*)(prow + t * 4);
    o[0] = __floats2half2_rn(v.x * inv, v.y * inv);
    o[1] = __floats2half2_rn(v.z * inv, v.w * inv);
}

// O[b] = P[b] @ Vt[b]^T : M=1024, N=512, K=1024 per batch (NT via Vt)
__global__ void __launch_bounds__(128, 2)
pv_kernel()
{
    const int b = blockIdx.z;
    const unsigned short* P  = g_p + (size_t)b * SEQ * SEQ;
    const unsigned short* Vt = g_vt + (size_t)b * SEQ * HID;
    unsigned short* O = g_o + (size_t)b * SEQ * HID;
    gemm_nt_f16<true>(P, Vt, nullptr, O, HID, SEQ,
                      blockIdx.y * BM, blockIdx.x * BN, false);
}

// out = relu(O @ Wo^T + bo) : M=32768, N=256, K=512 (fp32 out)
__global__ void __launch_bounds__(128, 2)
outproj_kernel(const float* __restrict__ bo, float* __restrict__ out)
{
    gemm_nt_f16<false>(g_o, g_wo, bo, out, DIN, HID,
                       blockIdx.y * BM, blockIdx.x * BN, true);
}

// ---------------------------------------------------------------------------
// Launch
// ---------------------------------------------------------------------------
extern "C" void kernel_launch(void* const* d_in, const int* in_sizes, int n_in,
                              void* d_out, int out_size)
{
    const float* h  = (const float*)d_in[0];
    const float* Wv = (const float*)d_in[1];
    const float* bv = (const float*)d_in[2];
    const float* Wk = (const float*)d_in[3];
    const float* bk = (const float*)d_in[4];
    const float* Wq = (const float*)d_in[5];
    const float* bq = (const float*)d_in[6];
    const float* Wo = (const float*)d_in[7];
    const float* bo = (const float*)d_in[8];
    float* out = (float*)d_out;

    static bool attr_done = false;
    if (!attr_done) {
        cudaFuncSetAttribute(qkv_kernel,     cudaFuncAttributeMaxDynamicSharedMemorySize, SMEM_DYN);
        cudaFuncSetAttribute(scores_kernel,  cudaFuncAttributeMaxDynamicSharedMemorySize, SMEM_DYN);
        cudaFuncSetAttribute(pv_kernel,      cudaFuncAttributeMaxDynamicSharedMemorySize, SMEM_DYN);
        cudaFuncSetAttribute(outproj_kernel, cudaFuncAttributeMaxDynamicSharedMemorySize, SMEM_DYN);
        attr_done = true;
    }

    unsigned short *ph, *pwq, *pwk, *pwv, *pwo;
    cudaGetSymbolAddress((void**)&ph,  g_h);
    cudaGetSymbolAddress((void**)&pwq, g_wq);
    cudaGetSymbolAddress((void**)&pwk, g_wk);
    cudaGetSymbolAddress((void**)&pwv, g_wv);
    cudaGetSymbolAddress((void**)&pwo, g_wo);

    // Convert inputs fp32 -> fp16
    cvt_half_kernel<<<(MTOT * DIN) / 1024, 256>>>(h, ph, MTOT * DIN);
    cvt_half_kernel<<<(HID * DIN) / 1024, 256>>>(Wq, pwq, HID * DIN);
    cvt_half_kernel<<<(HID * DIN) / 1024, 256>>>(Wk, pwk, HID * DIN);
    cvt_half_kernel<<<(HID * DIN) / 1024, 256>>>(Wv, pwv, HID * DIN);
    cvt_half_kernel<<<(DIN * HID) / 1024, 256>>>(Wo, pwo, DIN * HID);

    dim3 gQKV(HID / BN, MTOT / BM, 3);
    qkv_kernel<<<gQKV, 128, SMEM_DYN>>>(bq, bk, bv);

    dim3 gT(HID / 32, SEQ / 32, BATCH);
    transpose_kernel<<<gT, dim3(32, 8)>>>();

    dim3 gS(SEQ / BN, SEQ / BM, BATCH);
    scores_kernel<<<gS, 128, SMEM_DYN>>>();

    softmax_kernel<<<BATCH * SEQ, 256>>>();

    dim3 gPV(HID / BN, SEQ / BM, BATCH);
    pv_kernel<<<gPV, 128, SMEM_DYN>>>();

    dim3 gO(DIN / BN, MTOT / BM, 1);
    outproj_kernel<<<gO, 128, SMEM_DYN>>>(bo, out);
}

// round 16
// speedup vs baseline: 12.0584x; 1.0491x over previous
#include <cuda_runtime.h>
#include <cuda_fp16.h>
#include <cstddef>
#include <cstdint>

// Problem dims (fixed by the reference)
#define BATCH 32
#define SEQ   1024
#define DIN   256
#define HID   512
#define MTOT  (BATCH * SEQ)   // 32768

// GEMM tiling: block 128x128, BK=64 (fp16), 4 warps (2x2), warp tile 64x64
#define BM 128
#define BN 128
#define BK 64
#define ROWB 144               // smem row stride in bytes (16B-aligned, CF)
#define TILE_BYTES (BM * ROWB)             // 18432
#define SMEM_DYN (4 * TILE_BYTES)          // 73728 (A,B x 2 stages)

// Scratch in __device__ globals (allocation-free rule). Halfs as u16.
__device__ unsigned short g_h [(size_t)MTOT * DIN];
__device__ unsigned short g_wq[(size_t)HID * DIN];
__device__ unsigned short g_wk[(size_t)HID * DIN];
__device__ unsigned short g_wv[(size_t)HID * DIN];
__device__ unsigned short g_wo[(size_t)DIN * HID];
__device__ unsigned short g_q [(size_t)BATCH * SEQ * HID];
__device__ unsigned short g_k [(size_t)BATCH * SEQ * HID];
__device__ unsigned short g_v [(size_t)BATCH * SEQ * HID];
__device__ unsigned short g_vt[(size_t)BATCH * SEQ * HID];   // [b][hid][seq]
__device__ unsigned short g_o [(size_t)BATCH * SEQ * HID];
__device__ unsigned short g_p [(size_t)BATCH * SEQ * SEQ];   // softmax(P), fp16
__device__ float          g_s [(size_t)BATCH * SEQ * SEQ];   // logits, fp32

// ---------------------------------------------------------------------------
// PTX helpers
// ---------------------------------------------------------------------------
__device__ __forceinline__ uint32_t smaddr(const void* p) {
    return (uint32_t)__cvta_generic_to_shared(p);
}
__device__ __forceinline__ void cp16(void* s, const void* g) {
    asm volatile("cp.async.cg.shared.global [%0], [%1], 16;\n"
                 :: "r"(smaddr(s)), "l"(g));
}
__device__ __forceinline__ void cp_commit() { asm volatile("cp.async.commit_group;\n"); }
__device__ __forceinline__ void cp_wait1()  { asm volatile("cp.async.wait_group 1;\n"); }
__device__ __forceinline__ void cp_wait0()  { asm volatile("cp.async.wait_group 0;\n"); }
__device__ __forceinline__ void ldm_x4(uint32_t& r0, uint32_t& r1, uint32_t& r2,
                                       uint32_t& r3, uint32_t a) {
    asm volatile("ldmatrix.sync.aligned.m8n8.x4.shared.b16 {%0,%1,%2,%3}, [%4];"
                 : "=r"(r0), "=r"(r1), "=r"(r2), "=r"(r3) : "r"(a));
}
__device__ __forceinline__ void mma_f16(float& c0, float& c1, float& c2, float& c3,
                                        uint32_t a0, uint32_t a1, uint32_t a2, uint32_t a3,
                                        uint32_t b0, uint32_t b1) {
    asm volatile(
        "mma.sync.aligned.m16n8k16.row.col.f32.f16.f16.f32 "
        "{%0,%1,%2,%3}, {%4,%5,%6,%7}, {%8,%9}, {%0,%1,%2,%3};\n"
        : "+f"(c0), "+f"(c1), "+f"(c2), "+f"(c3)
        : "r"(a0), "r"(a1), "r"(a2), "r"(a3), "r"(b0), "r"(b1));
}

// ---------------------------------------------------------------------------
// fp16 NT GEMM body: C[M,N] = act(A[M,K] * B[N,K]^T + bias)
// A, B fp16 K-major. acc fp32. OUTH: store half, else fp32.
// Double-buffered cp.async staging, BK=64, ldmatrix.x4 fragment loads.
// ---------------------------------------------------------------------------
template<bool OUTH>
__device__ __forceinline__ void gemm_nt_f16(
    const unsigned short* __restrict__ A, const unsigned short* __restrict__ B,
    const float* __restrict__ bias, void* __restrict__ Cout,
    int N, int K, int m0, int n0, bool relu)
{
    extern __shared__ char sm[];
    const int t    = threadIdx.x;        // 0..127
    const int lane = t & 31;
    const int warp = t >> 5;             // 0..3
    const int wm   = (warp >> 1) * 64;   // 0,64
    const int wn   = (warp & 1) * 64;    // 0,64
    const int g4   = lane >> 2;          // 0..7
    const int l4   = lane & 3;           // 0..3

    float acc[4][8][4];
#pragma unroll
    for (int mt = 0; mt < 4; mt++)
#pragma unroll
        for (int nt = 0; nt < 8; nt++)
#pragma unroll
            for (int i = 0; i < 4; i++) acc[mt][nt][i] = 0.f;

    const int nchunks = K >> 6;

    auto stage = [&](int s, int kt) {
        char* Ad = sm + s * TILE_BYTES;
        char* Bd = sm + 2 * TILE_BYTES + s * TILE_BYTES;
        // tile = 128 rows x 64 halfs = 128B/row = 8 x 16B segs; 1024 segs total
#pragma unroll
        for (int i = 0; i < 8; i++) {
            const int seg = t + 128 * i;
            const int row = seg >> 3, sg = seg & 7;
            cp16(Ad + row * ROWB + sg * 16, A + (size_t)(m0 + row) * K + kt + sg * 8);
        }
#pragma unroll
        for (int i = 0; i < 8; i++) {
            const int seg = t + 128 * i;
            const int row = seg >> 3, sg = seg & 7;
            cp16(Bd + row * ROWB + sg * 16, B + (size_t)(n0 + row) * K + kt + sg * 8);
        }
    };

    // ldmatrix per-lane base offsets (bytes, within a stage)
    //  A x4: m0=rows r..r+7 @k8, m1=rows r+8..15 @k8, m2/m3 same rows @k8+16B
    const uint32_t aFrag = (uint32_t)((wm + (lane & 15)) * ROWB + (lane >> 4) * 16);
    //  B x4: m0=cols c..c+7 @k8, m1=@k8+16B, m2=cols c+8..15 @k8, m3=@+16B
    const uint32_t bFrag = (uint32_t)((wn + ((lane >> 4) << 3) + (lane & 7)) * ROWB +
                                      ((lane >> 3) & 1) * 16);
    const uint32_t sA0 = smaddr(sm);
    const uint32_t sB0 = smaddr(sm + 2 * TILE_BYTES);

    stage(0, 0);
    cp_commit();

    for (int c = 0; c < nchunks; ++c) {
        const int s = c & 1;
        if (c + 1 < nchunks) {
            stage(s ^ 1, (c + 1) << 6);
            cp_commit();
            cp_wait1();
        } else {
            cp_wait0();
        }
        __syncthreads();

        const uint32_t aBase = sA0 + s * TILE_BYTES + aFrag;
        const uint32_t bBase = sB0 + s * TILE_BYTES + bFrag;

#pragma unroll
        for (int ks = 0; ks < 4; ++ks) {
            const uint32_t koff = ks * 32;   // k16 group = 32 bytes
            uint32_t af[4][4];
#pragma unroll
            for (int mt = 0; mt < 4; mt++)
                ldm_x4(af[mt][0], af[mt][1], af[mt][2], af[mt][3],
                       aBase + mt * (16 * ROWB) + koff);
            uint32_t bf[8][2];
#pragma unroll
            for (int j = 0; j < 4; j++)
                ldm_x4(bf[2 * j][0], bf[2 * j][1], bf[2 * j + 1][0], bf[2 * j + 1][1],
                       bBase + j * (16 * ROWB) + koff);
#pragma unroll
            for (int mt = 0; mt < 4; mt++)
#pragma unroll
                for (int nt = 0; nt < 8; nt++)
                    mma_f16(acc[mt][nt][0], acc[mt][nt][1], acc[mt][nt][2], acc[mt][nt][3],
                            af[mt][0], af[mt][1], af[mt][2], af[mt][3],
                            bf[nt][0], bf[nt][1]);
        }
        __syncthreads();
    }

    // --- epilogue ---
#pragma unroll
    for (int mt = 0; mt < 4; mt++) {
        const int r = m0 + wm + mt * 16 + g4;
#pragma unroll
        for (int nt = 0; nt < 8; nt++) {
            const int col = n0 + wn + nt * 8 + 2 * l4;
            float bx = 0.f, by = 0.f;
            if (bias) { bx = bias[col]; by = bias[col + 1]; }
            float v0 = acc[mt][nt][0] + bx;
            float v1 = acc[mt][nt][1] + by;
            float v2 = acc[mt][nt][2] + bx;
            float v3 = acc[mt][nt][3] + by;
            if (relu) {
                v0 = fmaxf(v0, 0.f); v1 = fmaxf(v1, 0.f);
                v2 = fmaxf(v2, 0.f); v3 = fmaxf(v3, 0.f);
            }
            if (OUTH) {
                *(__half2*)((unsigned short*)Cout + (size_t)r * N + col)
                    = __floats2half2_rn(v0, v1);
                *(__half2*)((unsigned short*)Cout + (size_t)(r + 8) * N + col)
                    = __floats2half2_rn(v2, v3);
            } else {
                *(float2*)((float*)Cout + (size_t)r * N + col)       = make_float2(v0, v1);
                *(float2*)((float*)Cout + (size_t)(r + 8) * N + col) = make_float2(v2, v3);
            }
        }
    }
}

// ---------------------------------------------------------------------------
// Kernels
// ---------------------------------------------------------------------------

// fp32 -> fp16 convert (4 elems/thread)
__global__ void cvt_half_kernel(const float* __restrict__ in,
                                unsigned short* __restrict__ out, int n)
{
    const int i = (blockIdx.x * blockDim.x + threadIdx.x) * 4;
    if (i < n) {
        float4 v = *(const float4*)(in + i);
        __half2* o = (__half2*)(out + i);
        o[0] = __floats2half2_rn(v.x, v.y);
        o[1] = __floats2half2_rn(v.z, v.w);
    }
}

// All 4 weight matrices in one launch: blockIdx.y selects which.
__global__ void cvt_weights_kernel(const float* __restrict__ Wq,
                                   const float* __restrict__ Wk,
                                   const float* __restrict__ Wv,
                                   const float* __restrict__ Wo)
{
    const float* in;
    unsigned short* out;
    switch (blockIdx.y) {
        case 0: in = Wq; out = g_wq; break;
        case 1: in = Wk; out = g_wk; break;
        case 2: in = Wv; out = g_wv; break;
        default: in = Wo; out = g_wo; break;
    }
    const int i = (blockIdx.x * blockDim.x + threadIdx.x) * 4;
    float4 v = *(const float4*)(in + i);
    __half2* o = (__half2*)(out + i);
    o[0] = __floats2half2_rn(v.x, v.y);
    o[1] = __floats2half2_rn(v.z, v.w);
}

// z=0 -> q, z=1 -> k, z=2 -> v : relu(h @ W^T + b)  M=32768, N=512, K=256
__global__ void __launch_bounds__(128, 2)
qkv_kernel(const float* __restrict__ bq, const float* __restrict__ bk,
           const float* __restrict__ bv)
{
    const unsigned short* W; const float* bia; unsigned short* out;
    if (blockIdx.z == 0)      { W = g_wq; bia = bq; out = g_q; }
    else if (blockIdx.z == 1) { W = g_wk; bia = bk; out = g_k; }
    else                      { W = g_wv; bia = bv; out = g_v; }
    gemm_nt_f16<true>(g_h, W, bia, out, HID, DIN,
                      blockIdx.y * BM, blockIdx.x * BN, true);
}

// V[b][s][h] -> Vt[b][h][s]  (32x32 fp16 tiles)
__global__ void transpose_kernel()
{
    __shared__ unsigned short tile[32][34];
    const int b  = blockIdx.z;
    const int h0 = blockIdx.x * 32;
    const int s0 = blockIdx.y * 32;
    const int tx = threadIdx.x, ty = threadIdx.y;  // 32 x 8
    const unsigned short* V = g_v + (size_t)b * SEQ * HID;
    unsigned short* Vt = g_vt + (size_t)b * SEQ * HID;
#pragma unroll
    for (int i = 0; i < 4; i++)
        tile[ty + 8 * i][tx] = V[(size_t)(s0 + ty + 8 * i) * HID + h0 + tx];
    __syncthreads();
#pragma unroll
    for (int i = 0; i < 4; i++)
        Vt[(size_t)(h0 + ty + 8 * i) * SEQ + s0 + tx] = tile[tx][ty + 8 * i];
}

// S[b] = Q[b] @ K[b]^T : M=N=1024, K=512 per batch (fp32 logits out)
__global__ void __launch_bounds__(128, 2)
scores_kernel()
{
    const int b = blockIdx.z;
    const unsigned short* Q = g_q + (size_t)b * SEQ * HID;
    const unsigned short* K = g_k + (size_t)b * SEQ * HID;
    float* S = g_s + (size_t)b * SEQ * SEQ;
    gemm_nt_f16<false>(Q, K, nullptr, S, SEQ, HID,
                       blockIdx.y * BM, blockIdx.x * BN, false);
}

// Row softmax: fp32 logits in g_s -> fp16 probabilities in g_p
__global__ void softmax_kernel()
{
    __shared__ float red[8];
    const float* row = g_s + (size_t)blockIdx.x * SEQ;
    unsigned short* prow = g_p + (size_t)blockIdx.x * SEQ;
    const int t = threadIdx.x;
    const int lane = t & 31, warp = t >> 5;

    float4 v = *(const float4*)(row + t * 4);
    float m = fmaxf(fmaxf(v.x, v.y), fmaxf(v.z, v.w));
#pragma unroll
    for (int o = 16; o > 0; o >>= 1) m = fmaxf(m, __shfl_xor_sync(0xffffffffu, m, o));
    if (lane == 0) red[warp] = m;
    __syncthreads();
    if (warp == 0) {
        float mm = red[lane & 7];
#pragma unroll
        for (int o = 4; o > 0; o >>= 1) mm = fmaxf(mm, __shfl_xor_sync(0xffffffffu, mm, o));
        if (lane == 0) red[0] = mm;
    }
    __syncthreads();
    m = red[0];
    __syncthreads();

    v.x = expf(v.x - m); v.y = expf(v.y - m);
    v.z = expf(v.z - m); v.w = expf(v.w - m);
    float s = v.x + v.y + v.z + v.w;
#pragma unroll
    for (int o = 16; o > 0; o >>= 1) s += __shfl_xor_sync(0xffffffffu, s, o);
    if (lane == 0) red[warp] = s;
    __syncthreads();
    if (warp == 0) {
        float ss = red[lane & 7];
#pragma unroll
        for (int o = 4; o > 0; o >>= 1) ss += __shfl_xor_sync(0xffffffffu, ss, o);
        if (lane == 0) red[0] = ss;
    }
    __syncthreads();
    float inv = 1.0f / red[0];
    __half2* o = (__half2*)(prow + t * 4);
    o[0] = __floats2half2_rn(v.x * inv, v.y * inv);
    o[1] = __floats2half2_rn(v.z * inv, v.w * inv);
}

// O[b] = P[b] @ Vt[b]^T : M=1024, N=512, K=1024 per batch (NT via Vt)
__global__ void __launch_bounds__(128, 2)
pv_kernel()
{
    const int b = blockIdx.z;
    const unsigned short* P  = g_p + (size_t)b * SEQ * SEQ;
    const unsigned short* Vt = g_vt + (size_t)b * SEQ * HID;
    unsigned short* O = g_o + (size_t)b * SEQ * HID;
    gemm_nt_f16<true>(P, Vt, nullptr, O, HID, SEQ,
                      blockIdx.y * BM, blockIdx.x * BN, false);
}

// out = relu(O @ Wo^T + bo) : M=32768, N=256, K=512 (fp32 out)
__global__ void __launch_bounds__(128, 2)
outproj_kernel(const float* __restrict__ bo, float* __restrict__ out)
{
    gemm_nt_f16<false>(g_o, g_wo, bo, out, DIN, HID,
                       blockIdx.y * BM, blockIdx.x * BN, true);
}

// ---------------------------------------------------------------------------
// Launch
// ---------------------------------------------------------------------------
extern "C" void kernel_launch(void* const* d_in, const int* in_sizes, int n_in,
                              void* d_out, int out_size)
{
    const float* h  = (const float*)d_in[0];
    const float* Wv = (const float*)d_in[1];
    const float* bv = (const float*)d_in[2];
    const float* Wk = (const float*)d_in[3];
    const float* bk = (const float*)d_in[4];
    const float* Wq = (const float*)d_in[5];
    const float* bq = (const float*)d_in[6];
    const float* Wo = (const float*)d_in[7];
    const float* bo = (const float*)d_in[8];
    float* out = (float*)d_out;

    static bool attr_done = false;
    if (!attr_done) {
        cudaFuncSetAttribute(qkv_kernel,     cudaFuncAttributeMaxDynamicSharedMemorySize, SMEM_DYN);
        cudaFuncSetAttribute(scores_kernel,  cudaFuncAttributeMaxDynamicSharedMemorySize, SMEM_DYN);
        cudaFuncSetAttribute(pv_kernel,      cudaFuncAttributeMaxDynamicSharedMemorySize, SMEM_DYN);
        cudaFuncSetAttribute(outproj_kernel, cudaFuncAttributeMaxDynamicSharedMemorySize, SMEM_DYN);
        attr_done = true;
    }

    unsigned short* ph;
    cudaGetSymbolAddress((void**)&ph, g_h);

    // Convert inputs fp32 -> fp16
    cvt_half_kernel<<<(MTOT * DIN) / 1024, 256>>>(h, ph, MTOT * DIN);
    cvt_weights_kernel<<<dim3((HID * DIN) / 1024, 4), 256>>>(Wq, Wk, Wv, Wo);

    dim3 gQKV(HID / BN, MTOT / BM, 3);
    qkv_kernel<<<gQKV, 128, SMEM_DYN>>>(bq, bk, bv);

    dim3 gT(HID / 32, SEQ / 32, BATCH);
    transpose_kernel<<<gT, dim3(32, 8)>>>();

    dim3 gS(SEQ / BN, SEQ / BM, BATCH);
    scores_kernel<<<gS, 128, SMEM_DYN>>>();

    softmax_kernel<<<BATCH * SEQ, 256>>>();

    dim3 gPV(HID / BN, SEQ / BM, BATCH);
    pv_kernel<<<gPV, 128, SMEM_DYN>>>();

    dim3 gO(DIN / BN, MTOT / BM, 1);
    outproj_kernel<<<gO, 128, SMEM_DYN>>>(bo, out);
}